// round 10
// baseline (speedup 1.0000x reference)
#include <cuda_runtime.h>
#include <cstdint>
#include <cstddef>

#define N_NODES 100000
#define N_EDGES 120000
#define N_GRAPH 256
#define IN_DIM  162
#define HID     128
#define R_REL   5
#define NBLK    6            // root + 5 relations
#define DPAD0   192          // IN_DIM padded to 32
#define DPADH   128
#define PADK    36           // smem row stride (floats): conflict-free frag loads
#define CSTRIDE 132          // smem C-tile row stride (floats)

// ---------------- scratch (static __device__, no allocation) ----------------
__device__ float g_bufA[(size_t)N_NODES * HID];
__device__ float g_bufB[(size_t)N_NODES * HID];
__device__ float g_Bt[(size_t)NBLK * HID * DPAD0];     // transposed weights, K-major
__device__ int   g_cnt[R_REL * N_NODES];               // counts by dst (for invc)
__device__ int   g_cnt_src[R_REL * N_NODES];           // counts by src (for CSR)
__device__ float g_invc[R_REL * N_NODES];
__device__ int   g_rowptr[R_REL * (N_NODES + 1)];      // CSR by src
__device__ int   g_cur[R_REL * N_NODES];               // placement cursors
__device__ int2  g_es[(size_t)R_REL * N_EDGES];        // src-sorted (src,dst)
__device__ float g_read[N_GRAPH * HID];

// ---------------- setup kernels ----------------
__global__ void zero_cnt_kernel() {
    int i = blockIdx.x * blockDim.x + threadIdx.x;
    if (i < R_REL * N_NODES) { g_cnt[i] = 0; g_cnt_src[i] = 0; }
}
__global__ void count_kernel(const int* __restrict__ e1, const int* __restrict__ e2,
                             const int* __restrict__ e3, const int* __restrict__ e4,
                             const int* __restrict__ e5) {
    int r = blockIdx.y;
    const int* eis[R_REL] = {e1, e2, e3, e4, e5};
    const int* ei = eis[r];
    int e = blockIdx.x * blockDim.x + threadIdx.x;
    if (e < N_EDGES) {
        atomicAdd(&g_cnt[r * N_NODES + ei[N_EDGES + e]], 1);
        atomicAdd(&g_cnt_src[r * N_NODES + ei[e]], 1);
    }
}
__global__ void invc_kernel() {
    int i = blockIdx.x * blockDim.x + threadIdx.x;
    if (i < R_REL * N_NODES) {
        int c = g_cnt[i];
        g_invc[i] = 1.0f / (float)(c > 0 ? c : 1);
    }
}

// block-chunked exclusive scan of g_cnt_src -> g_rowptr, g_cur. blockIdx.x = relation.
__global__ __launch_bounds__(1024)
void scan_kernel() {
    const int r = blockIdx.x;
    __shared__ int warpsum[32];
    __shared__ int s_running;
    const int t = threadIdx.x, lane = t & 31, w = t >> 5;
    if (t == 0) s_running = 0;
    __syncthreads();
    for (int base = 0; base < N_NODES; base += 1024) {
        int i = base + t;
        int v = (i < N_NODES) ? g_cnt_src[r * N_NODES + i] : 0;
        int x = v;
#pragma unroll
        for (int o = 1; o < 32; o <<= 1) {
            int y = __shfl_up_sync(~0u, x, o);
            if (lane >= o) x += y;
        }
        if (lane == 31) warpsum[w] = x;
        __syncthreads();
        if (w == 0) {
            int s = warpsum[lane];
#pragma unroll
            for (int o = 1; o < 32; o <<= 1) {
                int y = __shfl_up_sync(~0u, s, o);
                if (lane >= o) s += y;
            }
            warpsum[lane] = s;
        }
        __syncthreads();
        int excl = s_running + (w > 0 ? warpsum[w - 1] : 0) + x - v;
        if (i < N_NODES) {
            g_rowptr[r * (N_NODES + 1) + i] = excl;
            g_cur[r * N_NODES + i] = excl;
        }
        __syncthreads();
        if (t == 0) s_running += warpsum[31];
        __syncthreads();
    }
    if (t == 0) g_rowptr[r * (N_NODES + 1) + N_NODES] = s_running;
}

__global__ void place_kernel(const int* __restrict__ e1, const int* __restrict__ e2,
                             const int* __restrict__ e3, const int* __restrict__ e4,
                             const int* __restrict__ e5) {
    int r = blockIdx.y;
    const int* eis[R_REL] = {e1, e2, e3, e4, e5};
    const int* ei = eis[r];
    int e = blockIdx.x * blockDim.x + threadIdx.x;
    if (e < N_EDGES) {
        int src = ei[e], dst = ei[N_EDGES + e];
        int pos = atomicAdd(&g_cur[r * N_NODES + src], 1);
        g_es[(size_t)r * N_EDGES + pos] = make_int2(src, dst);
    }
}

__global__ void zero_out_kernel(float* __restrict__ p, int n4) {
    int i = blockIdx.x * blockDim.x + threadIdx.x;
    if (i < n4) ((float4*)p)[i] = make_float4(0.f, 0.f, 0.f, 0.f);
}

// ---------------- weight transpose: g_Bt[c][j][k] = src_c[k][j], zero-padded k>=Din ----
__global__ void transpose_kernel(const float* __restrict__ root, const float* __restrict__ W,
                                 int Din, int Dpad) {
    __shared__ float tile[32][33];
    int c = blockIdx.z;
    const float* src = (c == 0) ? root : (W + (size_t)(c - 1) * Din * HID);
    int kt = blockIdx.x * 32, jt = blockIdx.y * 32;
    int tx = threadIdx.x, ty = threadIdx.y;  // 32 x 8
#pragma unroll
    for (int i = 0; i < 4; i++) {
        int k = kt + ty + i * 8, j = jt + tx;
        tile[ty + i * 8][tx] = (k < Din) ? src[(size_t)k * HID + j] : 0.0f;
    }
    __syncthreads();
#pragma unroll
    for (int i = 0; i < 4; i++) {
        int j = jt + ty + i * 8, k = kt + tx;
        g_Bt[((size_t)c * HID + j) * Dpad + k] = tile[tx][ty + i * 8];
    }
}

// ---------------- tf32 mma GEMM with fused edge scatter ----------------
__device__ __forceinline__ uint32_t f2tf(float f) {
    uint32_t u;
    asm("cvt.rna.tf32.f32 %0, %1;" : "=r"(u) : "f"(f));
    return u;
}

// smem: As[2][128][PADK], Bs[2][128][PADK] floats; reused as C[128][CSTRIDE] in epilogue
#define GEMM_SMEM (4 * 128 * PADK * 4)

__global__ __launch_bounds__(256, 1)
void gemm_mma_kernel(const float* __restrict__ A, int Din, int Dpad,
                     const float* __restrict__ bias,
                     float* __restrict__ out, int applyRelu) {
    extern __shared__ float sm[];
    float* Asm = sm;                       // [2][128][PADK]
    float* Bsm = sm + 2 * 128 * PADK;      // [2][128][PADK]

    const int c = blockIdx.x;              // 0..5 (fast dim -> A tile L2 reuse)
    const int rowBase = blockIdx.y * 128;
    const int t = threadIdx.x;
    const int wid = t >> 5, lane = t & 31;
    const int warpM = wid >> 2;            // 0..1 (64 rows each)
    const int warpN = wid & 3;             // 0..3 (32 cols each)
    const int lr = lane >> 2;              // 0..7
    const int lc = lane & 3;               // 0..3

    const float* Bt = g_Bt + (size_t)c * HID * Dpad;
    const int nK = Dpad >> 5;

    float cacc[4][4][4];
#pragma unroll
    for (int mt = 0; mt < 4; mt++)
#pragma unroll
        for (int nt = 0; nt < 4; nt++)
#pragma unroll
            for (int q = 0; q < 4; q++) cacc[mt][nt][q] = 0.0f;

    float ar[8][2];     // staging: A 128x32, 8 float2 per thread
    float br[4][4];     // staging: B 128x32, 4 float4 per thread

#define LOADG(I) do {                                                            \
        const int k0_ = (I) * 32;                                                \
        _Pragma("unroll")                                                        \
        for (int p = 0; p < 8; p++) {                                            \
            int lin = p * 256 + t;                                               \
            int row = lin >> 4, c2 = lin & 15;                                   \
            int gr = rowBase + row, gk = k0_ + c2 * 2;                           \
            float2 v = make_float2(0.f, 0.f);                                    \
            if (gr < N_NODES && gk < Din)                                        \
                v = *(const float2*)(A + (size_t)gr * Din + gk);                 \
            if (applyRelu) { v.x = fmaxf(v.x, 0.f); v.y = fmaxf(v.y, 0.f); }     \
            ar[p][0] = v.x; ar[p][1] = v.y;                                      \
        }                                                                        \
        _Pragma("unroll")                                                        \
        for (int p = 0; p < 4; p++) {                                            \
            int lin = p * 256 + t;                                               \
            int j = lin >> 3, c4 = lin & 7;                                      \
            const float4 v = *(const float4*)(Bt + (size_t)j * Dpad + k0_ + c4 * 4); \
            br[p][0] = v.x; br[p][1] = v.y; br[p][2] = v.z; br[p][3] = v.w;      \
        }                                                                        \
    } while (0)

#define STORES(B) do {                                                           \
        float* Ab = Asm + (B) * 128 * PADK;                                      \
        float* Bb = Bsm + (B) * 128 * PADK;                                      \
        _Pragma("unroll")                                                        \
        for (int p = 0; p < 8; p++) {                                            \
            int lin = p * 256 + t;                                               \
            int row = lin >> 4, c2 = lin & 15;                                   \
            uint2 u = make_uint2(f2tf(ar[p][0]), f2tf(ar[p][1]));                \
            *(uint2*)(Ab + row * PADK + c2 * 2) = u;                             \
        }                                                                        \
        _Pragma("unroll")                                                        \
        for (int p = 0; p < 4; p++) {                                            \
            int lin = p * 256 + t;                                               \
            int j = lin >> 3, c4 = lin & 7;                                      \
            uint4 u = make_uint4(f2tf(br[p][0]), f2tf(br[p][1]),                 \
                                 f2tf(br[p][2]), f2tf(br[p][3]));                \
            *(uint4*)(Bb + j * PADK + c4 * 4) = u;                               \
        }                                                                        \
    } while (0)

#define COMPUTE(B) do {                                                          \
        const float* Ab = Asm + (B) * 128 * PADK + (warpM * 64 + lr) * PADK + lc;\
        const float* Bb = Bsm + (B) * 128 * PADK + (warpN * 32 + lr) * PADK + lc;\
        _Pragma("unroll")                                                        \
        for (int ks = 0; ks < 4; ks++) {                                         \
            const int k0_ = ks * 8;                                              \
            uint32_t afr[4][4], bfr[4][2];                                       \
            _Pragma("unroll")                                                    \
            for (int mt = 0; mt < 4; mt++) {                                     \
                const float* pa = Ab + mt * 16 * PADK + k0_;                     \
                afr[mt][0] = *(const uint32_t*)(pa);                             \
                afr[mt][1] = *(const uint32_t*)(pa + 8 * PADK);                  \
                afr[mt][2] = *(const uint32_t*)(pa + 4);                         \
                afr[mt][3] = *(const uint32_t*)(pa + 8 * PADK + 4);              \
            }                                                                    \
            _Pragma("unroll")                                                    \
            for (int nt = 0; nt < 4; nt++) {                                     \
                const float* pb = Bb + nt * 8 * PADK + k0_;                      \
                bfr[nt][0] = *(const uint32_t*)(pb);                             \
                bfr[nt][1] = *(const uint32_t*)(pb + 4);                         \
            }                                                                    \
            _Pragma("unroll")                                                    \
            for (int mt = 0; mt < 4; mt++)                                       \
                _Pragma("unroll")                                                \
                for (int nt = 0; nt < 4; nt++) {                                 \
                    asm volatile(                                                \
                        "mma.sync.aligned.m16n8k8.row.col.f32.tf32.tf32.f32 "    \
                        "{%0,%1,%2,%3}, {%4,%5,%6,%7}, {%8,%9}, {%0,%1,%2,%3};"  \
                        : "+f"(cacc[mt][nt][0]), "+f"(cacc[mt][nt][1]),          \
                          "+f"(cacc[mt][nt][2]), "+f"(cacc[mt][nt][3])           \
                        : "r"(afr[mt][0]), "r"(afr[mt][1]),                      \
                          "r"(afr[mt][2]), "r"(afr[mt][3]),                      \
                          "r"(bfr[nt][0]), "r"(bfr[nt][1]));                     \
                }                                                                \
        }                                                                        \
    } while (0)

    // prologue
    LOADG(0);
    STORES(0);
    __syncthreads();

    for (int i = 0; i < nK; i++) {
        if (i + 1 < nK) LOADG(i + 1);
        COMPUTE(i & 1);
        __syncthreads();
        if (i + 1 < nK) {
            STORES((i + 1) & 1);
            __syncthreads();
        }
    }

    // ---- epilogue: dump C tile to smem (mainloop buffers dead after last sync) ----
    float* Cs = sm;   // [128][CSTRIDE]
#pragma unroll
    for (int mt = 0; mt < 4; mt++)
#pragma unroll
        for (int half = 0; half < 2; half++)
#pragma unroll
            for (int nt = 0; nt < 4; nt++) {
                int row = warpM * 64 + mt * 16 + half * 8 + lr;
                int col = warpN * 32 + nt * 8 + lc * 2;
                Cs[row * CSTRIDE + col]     = cacc[mt][nt][half * 2 + 0];
                Cs[row * CSTRIDE + col + 1] = cacc[mt][nt][half * 2 + 1];
            }
    __syncthreads();

    if (c == 0) {
        // self term + bias: red into pre-zeroed out
#pragma unroll
        for (int p = 0; p < 16; p++) {
            int lin = p * 256 + t;       // 0..4095 float4 slots
            int row = lin >> 5;          // 32 float4 per row
            int c4 = lin & 31;
            int gr = rowBase + row;
            if (gr < N_NODES) {
                float4 v = *(const float4*)(Cs + row * CSTRIDE + c4 * 4);
                const float4 b4 = *(const float4*)(bias + c4 * 4);
                v.x += b4.x; v.y += b4.y; v.z += b4.z; v.w += b4.w;
                float* p4 = out + (size_t)gr * HID + c4 * 4;
                asm volatile("red.global.add.v4.f32 [%0], {%1,%2,%3,%4};"
                             :: "l"(p4), "f"(v.x), "f"(v.y), "f"(v.z), "f"(v.w)
                             : "memory");
            }
        }
    } else {
        // fused scatter: edges with src in this tile
        const int rr = c - 1;
        const int tileEnd = (rowBase + 128 < N_NODES) ? (rowBase + 128) : N_NODES;
        const int lo = g_rowptr[rr * (N_NODES + 1) + rowBase];
        const int hi = g_rowptr[rr * (N_NODES + 1) + tileEnd];
        const int2* es = g_es + (size_t)rr * N_EDGES;
        for (int e = lo + wid; e < hi; e += 8) {
            int2 sd = es[e];
            float sc = __ldg(&g_invc[rr * N_NODES + sd.y]);
            const float4 m = *(const float4*)(Cs + (sd.x - rowBase) * CSTRIDE + lane * 4);
            float4 v;
            v.x = m.x * sc; v.y = m.y * sc; v.z = m.z * sc; v.w = m.w * sc;
            float* p4 = out + (size_t)sd.y * HID + lane * 4;
            asm volatile("red.global.add.v4.f32 [%0], {%1,%2,%3,%4};"
                         :: "l"(p4), "f"(v.x), "f"(v.y), "f"(v.z), "f"(v.w)
                         : "memory");
        }
    }
#undef LOADG
#undef STORES
#undef COMPUTE
}

// ---------------- graph readout (batch sorted); applies final ReLU ----------------
__device__ __forceinline__ int lower_bound_dev(const int* a, int n, int key) {
    int lo = 0, hi = n;
    while (lo < hi) {
        int mid = (lo + hi) >> 1;
        if (a[mid] < key) lo = mid + 1; else hi = mid;
    }
    return lo;
}
__global__ void readout_kernel(const float* __restrict__ h, const int* __restrict__ batch) {
    int g = blockIdx.x;
    int j = threadIdx.x;  // 128
    int lo = lower_bound_dev(batch, N_NODES, g);
    int hi = lower_bound_dev(batch, N_NODES, g + 1);
    float s = 0.0f;
    for (int n = lo; n < hi; n++) s += fmaxf(h[(size_t)n * HID + j], 0.0f);
    int c = hi - lo;
    g_read[g * HID + j] = s / (float)(c > 0 ? c : 1);
}

// ---------------- fused MLP head ----------------
__global__ void mlp_kernel(const float* __restrict__ Wc1, const float* __restrict__ bc1,
                           const float* __restrict__ Wc2, const float* __restrict__ bc2,
                           const float* __restrict__ Wc3, const float* __restrict__ bc3,
                           float* __restrict__ out) {
    int g = blockIdx.x;
    int j = threadIdx.x;  // 128
    __shared__ float row[HID];
    __shared__ float h1[HID];
    __shared__ float h2[HID];

    row[j] = g_read[g * HID + j];
    __syncthreads();

    float acc = bc1[j];
    for (int f = 0; f < HID; f++) acc = fmaf(row[f], Wc1[f * HID + j], acc);
    h1[j] = fmaxf(acc, 0.f);
    __syncthreads();

    acc = bc2[j];
    for (int f = 0; f < HID; f++) acc = fmaf(h1[f], Wc2[f * HID + j], acc);
    h2[j] = fmaxf(acc, 0.f) * Wc3[j];
    __syncthreads();

    for (int s = 64; s > 0; s >>= 1) {
        if (j < s) h2[j] += h2[j + s];
        __syncthreads();
    }
    if (j == 0) out[g] = h2[0] + bc3[0];
}

// ---------------- launch ----------------
extern "C" void kernel_launch(void* const* d_in, const int* in_sizes, int n_in,
                              void* d_out, int out_size) {
    const float* X = (const float*)d_in[0];
    const int* e[R_REL];
    const int* batch;
    if (in_sizes[1] == 2 * N_EDGES) {
        for (int r = 0; r < R_REL; r++) e[r] = (const int*)d_in[1 + r];
        batch = (const int*)d_in[6];
    } else {
        batch = (const int*)d_in[1];
        for (int r = 0; r < R_REL; r++) e[r] = (const int*)d_in[2 + r];
    }
    const float* W0    = (const float*)d_in[7];
    const float* root0 = (const float*)d_in[8];
    const float* b0    = (const float*)d_in[9];
    const float* Wl    = (const float*)d_in[10];
    const float* rootl = (const float*)d_in[11];
    const float* bl    = (const float*)d_in[12];
    const float* Wc1   = (const float*)d_in[13];
    const float* bc1   = (const float*)d_in[14];
    const float* Wc2   = (const float*)d_in[15];
    const float* bc2   = (const float*)d_in[16];
    const float* Wc3   = (const float*)d_in[17];
    const float* bc3   = (const float*)d_in[18];
    float*       out   = (float*)d_out;

    float* bufA; cudaGetSymbolAddress((void**)&bufA, g_bufA);
    float* bufB; cudaGetSymbolAddress((void**)&bufB, g_bufB);

    cudaFuncSetAttribute(gemm_mma_kernel, cudaFuncAttributeMaxDynamicSharedMemorySize, GEMM_SMEM);

    // ---- setup: counts -> invc, src-CSR (fixed across layers) ----
    zero_cnt_kernel<<<(R_REL * N_NODES + 255) / 256, 256>>>();
    {
        dim3 grid((N_EDGES + 255) / 256, R_REL);
        count_kernel<<<grid, 256>>>(e[0], e[1], e[2], e[3], e[4]);
    }
    invc_kernel<<<(R_REL * N_NODES + 255) / 256, 256>>>();
    scan_kernel<<<R_REL, 1024>>>();
    {
        dim3 grid((N_EDGES + 255) / 256, R_REL);
        place_kernel<<<grid, 256>>>(e[0], e[1], e[2], e[3], e[4]);
    }

    const int gemmRows = (N_NODES + 127) / 128;  // 782
    dim3 gemmGrid(NBLK, gemmRows);               // c fast -> A tile L2 reuse
    dim3 tpBlock(32, 8);
    const int outN4 = N_NODES * HID / 4;
    const int zBlocks = (outN4 + 255) / 256;

    // layer 0: X (N x 162) -> bufA
    transpose_kernel<<<dim3(DPAD0 / 32, 4, NBLK), tpBlock>>>(root0, W0, IN_DIM, DPAD0);
    zero_out_kernel<<<zBlocks, 256>>>(bufA, outN4);
    gemm_mma_kernel<<<gemmGrid, 256, GEMM_SMEM>>>(X, IN_DIM, DPAD0, b0, bufA, 0);

    // layer 1: bufA -> bufB (relu on load)
    transpose_kernel<<<dim3(DPADH / 32, 4, NBLK), tpBlock>>>(rootl, Wl, HID, DPADH);
    zero_out_kernel<<<zBlocks, 256>>>(bufB, outN4);
    gemm_mma_kernel<<<gemmGrid, 256, GEMM_SMEM>>>(bufA, HID, DPADH, bl, bufB, 1);

    // layer 2: bufB -> bufA (relu on load)
    transpose_kernel<<<dim3(DPADH / 32, 4, NBLK), tpBlock>>>(rootl + (size_t)HID * HID,
                                                             Wl + (size_t)R_REL * HID * HID,
                                                             HID, DPADH);
    zero_out_kernel<<<zBlocks, 256>>>(bufA, outN4);
    gemm_mma_kernel<<<gemmGrid, 256, GEMM_SMEM>>>(bufB, HID, DPADH, bl + HID, bufA, 1);

    // readout (with ReLU) + MLP head
    readout_kernel<<<N_GRAPH, HID>>>(bufA, batch);
    mlp_kernel<<<N_GRAPH, HID>>>(Wc1, bc1, Wc2, bc2, Wc3, bc3, out);
}

// round 11
// speedup vs baseline: 1.4589x; 1.4589x over previous
#include <cuda_runtime.h>
#include <cstdint>
#include <cstddef>

#define N_NODES 100000
#define N_EDGES 120000
#define N_GRAPH 256
#define IN_DIM  162
#define HID     128
#define R_REL   5
#define NBLK    6            // root + 5 relations
#define DPAD0   192          // IN_DIM padded to 32
#define DPADH   128
#define PADK    36           // smem row stride (floats): conflict-free frag loads

// ---------------- scratch (static __device__, no allocation) ----------------
__device__ float g_bufA[(size_t)N_NODES * HID];
__device__ float g_bufB[(size_t)N_NODES * HID];
__device__ float g_M[(size_t)R_REL * N_NODES * HID];   // per-relation messages
__device__ float g_Ar[(size_t)N_NODES * DPAD0];        // pre-rounded padded A
__device__ float g_Bt[(size_t)NBLK * HID * DPAD0];     // transposed pre-rounded weights
__device__ int   g_cnt[R_REL * N_NODES];
__device__ float g_invc[R_REL * N_NODES];
__device__ float g_read[N_GRAPH * HID];

// ---------------- helpers ----------------
__device__ __forceinline__ uint32_t f2tf(float f) {
    uint32_t u;
    asm("cvt.rna.tf32.f32 %0, %1;" : "=r"(u) : "f"(f));
    return u;
}
__device__ __forceinline__ uint32_t smem_u32(const void* p) {
    uint32_t a;
    asm("{ .reg .u64 t; cvta.to.shared.u64 t, %1; cvt.u32.u64 %0, t; }" : "=r"(a) : "l"(p));
    return a;
}
__device__ __forceinline__ void cp_async16(uint32_t dst, const void* src, bool valid) {
    int sz = valid ? 16 : 0;
    asm volatile("cp.async.cg.shared.global [%0], [%1], 16, %2;"
                 :: "r"(dst), "l"(src), "r"(sz));
}
#define CP_COMMIT() asm volatile("cp.async.commit_group;" ::: "memory")
#define CP_WAIT(n)  asm volatile("cp.async.wait_group %0;" :: "n"(n) : "memory")

// ---------------- setup kernels ----------------
__global__ void zero_cnt_kernel() {
    int i = blockIdx.x * blockDim.x + threadIdx.x;
    if (i < R_REL * N_NODES) g_cnt[i] = 0;
}
__global__ void count_kernel(const int* __restrict__ e1, const int* __restrict__ e2,
                             const int* __restrict__ e3, const int* __restrict__ e4,
                             const int* __restrict__ e5) {
    int r = blockIdx.y;
    const int* eis[R_REL] = {e1, e2, e3, e4, e5};
    const int* ei = eis[r];
    int e = blockIdx.x * blockDim.x + threadIdx.x;
    if (e < N_EDGES) atomicAdd(&g_cnt[r * N_NODES + ei[N_EDGES + e]], 1);
}
__global__ void invc_kernel() {
    int i = blockIdx.x * blockDim.x + threadIdx.x;
    if (i < R_REL * N_NODES) {
        int c = g_cnt[i];
        g_invc[i] = 1.0f / (float)(c > 0 ? c : 1);
    }
}

// ---------------- A pre-pass: pad + (relu) + tf32 round into g_Ar ----------------
template<int DIN, int DPAD, bool RELU>
__global__ void round_kernel(const float* __restrict__ in) {
    size_t i = (size_t)blockIdx.x * blockDim.x + threadIdx.x;
    if (i >= (size_t)N_NODES * DPAD) return;
    int row = (int)(i / DPAD), col = (int)(i % DPAD);
    float v = 0.0f;
    if (DIN == DPAD) v = in[i];
    else if (col < DIN) v = in[(size_t)row * DIN + col];
    if (RELU) v = fmaxf(v, 0.0f);
    ((uint32_t*)g_Ar)[i] = f2tf(v);
}

// ---------------- weight transpose + round: g_Bt[c][j][k] = tf32(src_c[k][j]) ----------------
__global__ void transpose_kernel(const float* __restrict__ root, const float* __restrict__ W,
                                 int Din, int Dpad) {
    __shared__ float tile[32][33];
    int c = blockIdx.z;
    const float* src = (c == 0) ? root : (W + (size_t)(c - 1) * Din * HID);
    int kt = blockIdx.x * 32, jt = blockIdx.y * 32;
    int tx = threadIdx.x, ty = threadIdx.y;  // 32 x 8
#pragma unroll
    for (int i = 0; i < 4; i++) {
        int k = kt + ty + i * 8, j = jt + tx;
        tile[ty + i * 8][tx] = (k < Din) ? src[(size_t)k * HID + j] : 0.0f;
    }
    __syncthreads();
#pragma unroll
    for (int i = 0; i < 4; i++) {
        int j = jt + ty + i * 8, k = kt + tx;
        ((uint32_t*)g_Bt)[((size_t)c * HID + j) * Dpad + k] = f2tf(tile[tx][ty + i * 8]);
    }
}

// ---------------- tf32 mma GEMM, cp.async 3-stage pipeline ----------------
// per stage: A[128][PADK] + B[128][PADK] floats = 36864 B; 3 stages = 110592 B
#define STAGE_BYTES  36864
#define STAGE_FLOATS 9216
#define GEMM_SMEM    (3 * STAGE_BYTES)

__global__ __launch_bounds__(256, 2)
void gemm_mma_kernel(int Dpad, const float* __restrict__ bias,
                     float* __restrict__ outSelf) {
    extern __shared__ float sm[];
    const uint32_t smemU = smem_u32(sm);

    const int c = blockIdx.x;              // 0..5 (fast dim -> A tile L2 reuse)
    const int rowBase = blockIdx.y * 128;
    const int t = threadIdx.x;
    const int wid = t >> 5, lane = t & 31;
    const int warpM = wid >> 2;            // 0..1 (64 rows each)
    const int warpN = wid & 3;             // 0..3 (32 cols each)
    const int lr = lane >> 2;              // 0..7
    const int lc = lane & 3;               // 0..3

    const float* Aar = g_Ar;
    const float* Bt = g_Bt + (size_t)c * HID * Dpad;
    const int nK = Dpad >> 5;

    float cacc[4][4][4];
#pragma unroll
    for (int mt = 0; mt < 4; mt++)
#pragma unroll
        for (int nt = 0; nt < 4; nt++)
#pragma unroll
            for (int q = 0; q < 4; q++) cacc[mt][nt][q] = 0.0f;

    // prefetch mapping: 1024 16B chunks per tile, 4 per thread
    const int chRow = t >> 1;              // rows: threads 0..255 -> 2 chunk-cols each? no:
    // use linear chunk ids: ch = p*256 + t; row = ch>>3, seg = ch&7
#define PREFETCH(I) do {                                                          \
        const int k0_ = (I) * 32;                                                 \
        const uint32_t sA = smemU + ((I) % 3) * STAGE_BYTES;                      \
        const uint32_t sB = sA + STAGE_BYTES / 2;                                 \
        _Pragma("unroll")                                                         \
        for (int p = 0; p < 4; p++) {                                             \
            int ch = p * 256 + t;                                                 \
            int row = ch >> 3, seg = ch & 7;                                      \
            const float* srcA = Aar + (size_t)(rowBase + row) * Dpad + k0_ + seg * 4; \
            cp_async16(sA + row * 144 + seg * 16, srcA, (rowBase + row) < N_NODES);   \
            const float* srcB = Bt + (size_t)row * Dpad + k0_ + seg * 4;          \
            cp_async16(sB + row * 144 + seg * 16, srcB, true);                    \
        }                                                                         \
    } while (0)

#define COMPUTE(S) do {                                                           \
        const float* Ab = sm + (S) * STAGE_FLOATS + (warpM * 64 + lr) * PADK + lc;\
        const float* Bb = sm + (S) * STAGE_FLOATS + STAGE_FLOATS / 2              \
                          + (warpN * 32 + lr) * PADK + lc;                        \
        _Pragma("unroll")                                                         \
        for (int ks = 0; ks < 4; ks++) {                                          \
            const int k0_ = ks * 8;                                               \
            uint32_t afr[4][4], bfr[4][2];                                        \
            _Pragma("unroll")                                                     \
            for (int mt = 0; mt < 4; mt++) {                                      \
                const float* pa = Ab + mt * 16 * PADK + k0_;                      \
                afr[mt][0] = *(const uint32_t*)(pa);                              \
                afr[mt][1] = *(const uint32_t*)(pa + 8 * PADK);                   \
                afr[mt][2] = *(const uint32_t*)(pa + 4);                          \
                afr[mt][3] = *(const uint32_t*)(pa + 8 * PADK + 4);               \
            }                                                                     \
            _Pragma("unroll")                                                     \
            for (int nt = 0; nt < 4; nt++) {                                      \
                const float* pb = Bb + nt * 8 * PADK + k0_;                       \
                bfr[nt][0] = *(const uint32_t*)(pb);                              \
                bfr[nt][1] = *(const uint32_t*)(pb + 4);                          \
            }                                                                     \
            _Pragma("unroll")                                                     \
            for (int mt = 0; mt < 4; mt++)                                        \
                _Pragma("unroll")                                                 \
                for (int nt = 0; nt < 4; nt++) {                                  \
                    asm volatile(                                                 \
                        "mma.sync.aligned.m16n8k8.row.col.f32.tf32.tf32.f32 "     \
                        "{%0,%1,%2,%3}, {%4,%5,%6,%7}, {%8,%9}, {%0,%1,%2,%3};"   \
                        : "+f"(cacc[mt][nt][0]), "+f"(cacc[mt][nt][1]),           \
                          "+f"(cacc[mt][nt][2]), "+f"(cacc[mt][nt][3])            \
                        : "r"(afr[mt][0]), "r"(afr[mt][1]),                       \
                          "r"(afr[mt][2]), "r"(afr[mt][3]),                       \
                          "r"(bfr[nt][0]), "r"(bfr[nt][1]));                      \
                }                                                                 \
        }                                                                         \
    } while (0)

    // prologue: prefetch 2 stages ahead
    PREFETCH(0); CP_COMMIT();
    PREFETCH(1); CP_COMMIT();

    int s = 0;
    for (int i = 0; i < nK; i++) {
        if (i + 2 < nK) { PREFETCH(i + 2); CP_COMMIT(); CP_WAIT(2); }
        else if (i + 1 < nK) { CP_WAIT(1); }
        else { CP_WAIT(0); }
        __syncthreads();
        COMPUTE(s);
        __syncthreads();
        if (++s == 3) s = 0;
    }

    // epilogue: direct stores (c-frag m16n8: c0/c1 row=lr col=2lc; c2/c3 row+8)
#pragma unroll
    for (int mt = 0; mt < 4; mt++) {
#pragma unroll
        for (int half = 0; half < 2; half++) {
            int gr = rowBase + warpM * 64 + mt * 16 + lr + half * 8;
            if (gr < N_NODES) {
                float* dst = (c == 0) ? (outSelf + (size_t)gr * HID)
                                      : (g_M + ((size_t)(c - 1) * N_NODES + gr) * HID);
#pragma unroll
                for (int nt = 0; nt < 4; nt++) {
                    int col = warpN * 32 + nt * 8 + lc * 2;
                    float2 v;
                    v.x = cacc[mt][nt][half * 2 + 0];
                    v.y = cacc[mt][nt][half * 2 + 1];
                    if (c == 0) { v.x += bias[col]; v.y += bias[col + 1]; }
                    *(float2*)(dst + col) = v;
                }
            }
        }
    }
#undef PREFETCH
#undef COMPUTE
}

// ---------------- edge scatter: out[dst] += M[r][src] * invc[r][dst] ----------------
__global__ void scatter_kernel(const int* __restrict__ e1, const int* __restrict__ e2,
                               const int* __restrict__ e3, const int* __restrict__ e4,
                               const int* __restrict__ e5,
                               float* __restrict__ out) {
    int r = blockIdx.y;
    const int* eis[R_REL] = {e1, e2, e3, e4, e5};
    const int* ei = eis[r];

    int warp = (blockIdx.x * blockDim.x + threadIdx.x) >> 5;
    int lane = threadIdx.x & 31;
    if (warp >= N_EDGES) return;

    int src = ei[warp];
    int dst = ei[N_EDGES + warp];
    float sc = __ldg(&g_invc[r * N_NODES + dst]);

    const float4 m = *(const float4*)(g_M + ((size_t)r * N_NODES + src) * HID + lane * 4);
    float4 v;
    v.x = m.x * sc; v.y = m.y * sc; v.z = m.z * sc; v.w = m.w * sc;

    float* p = out + (size_t)dst * HID + lane * 4;
    asm volatile("red.global.add.v4.f32 [%0], {%1,%2,%3,%4};"
                 :: "l"(p), "f"(v.x), "f"(v.y), "f"(v.z), "f"(v.w)
                 : "memory");
}

// ---------------- graph readout (batch sorted); applies final ReLU ----------------
__device__ __forceinline__ int lower_bound_dev(const int* a, int n, int key) {
    int lo = 0, hi = n;
    while (lo < hi) {
        int mid = (lo + hi) >> 1;
        if (a[mid] < key) lo = mid + 1; else hi = mid;
    }
    return lo;
}
__global__ void readout_kernel(const float* __restrict__ h, const int* __restrict__ batch) {
    int g = blockIdx.x;
    int j = threadIdx.x;  // 128
    int lo = lower_bound_dev(batch, N_NODES, g);
    int hi = lower_bound_dev(batch, N_NODES, g + 1);
    float s = 0.0f;
    for (int n = lo; n < hi; n++) s += fmaxf(h[(size_t)n * HID + j], 0.0f);
    int c = hi - lo;
    g_read[g * HID + j] = s / (float)(c > 0 ? c : 1);
}

// ---------------- fused MLP head ----------------
__global__ void mlp_kernel(const float* __restrict__ Wc1, const float* __restrict__ bc1,
                           const float* __restrict__ Wc2, const float* __restrict__ bc2,
                           const float* __restrict__ Wc3, const float* __restrict__ bc3,
                           float* __restrict__ out) {
    int g = blockIdx.x;
    int j = threadIdx.x;  // 128
    __shared__ float row[HID];
    __shared__ float h1[HID];
    __shared__ float h2[HID];

    row[j] = g_read[g * HID + j];
    __syncthreads();

    float acc = bc1[j];
    for (int f = 0; f < HID; f++) acc = fmaf(row[f], Wc1[f * HID + j], acc);
    h1[j] = fmaxf(acc, 0.f);
    __syncthreads();

    acc = bc2[j];
    for (int f = 0; f < HID; f++) acc = fmaf(h1[f], Wc2[f * HID + j], acc);
    h2[j] = fmaxf(acc, 0.f) * Wc3[j];
    __syncthreads();

    for (int s = 64; s > 0; s >>= 1) {
        if (j < s) h2[j] += h2[j + s];
        __syncthreads();
    }
    if (j == 0) out[g] = h2[0] + bc3[0];
}

// ---------------- launch ----------------
extern "C" void kernel_launch(void* const* d_in, const int* in_sizes, int n_in,
                              void* d_out, int out_size) {
    const float* X = (const float*)d_in[0];
    const int* e[R_REL];
    const int* batch;
    if (in_sizes[1] == 2 * N_EDGES) {
        for (int r = 0; r < R_REL; r++) e[r] = (const int*)d_in[1 + r];
        batch = (const int*)d_in[6];
    } else {
        batch = (const int*)d_in[1];
        for (int r = 0; r < R_REL; r++) e[r] = (const int*)d_in[2 + r];
    }
    const float* W0    = (const float*)d_in[7];
    const float* root0 = (const float*)d_in[8];
    const float* b0    = (const float*)d_in[9];
    const float* Wl    = (const float*)d_in[10];
    const float* rootl = (const float*)d_in[11];
    const float* bl    = (const float*)d_in[12];
    const float* Wc1   = (const float*)d_in[13];
    const float* bc1   = (const float*)d_in[14];
    const float* Wc2   = (const float*)d_in[15];
    const float* bc2   = (const float*)d_in[16];
    const float* Wc3   = (const float*)d_in[17];
    const float* bc3   = (const float*)d_in[18];
    float*       out   = (float*)d_out;

    float* bufA; cudaGetSymbolAddress((void**)&bufA, g_bufA);
    float* bufB; cudaGetSymbolAddress((void**)&bufB, g_bufB);

    cudaFuncSetAttribute(gemm_mma_kernel, cudaFuncAttributeMaxDynamicSharedMemorySize, GEMM_SMEM);

    // ---- setup: counts -> invc (fixed across layers) ----
    zero_cnt_kernel<<<(R_REL * N_NODES + 255) / 256, 256>>>();
    {
        dim3 grid((N_EDGES + 255) / 256, R_REL);
        count_kernel<<<grid, 256>>>(e[0], e[1], e[2], e[3], e[4]);
    }
    invc_kernel<<<(R_REL * N_NODES + 255) / 256, 256>>>();

    const int gemmRows = (N_NODES + 127) / 128;  // 782
    dim3 gemmGrid(NBLK, gemmRows);               // c fast -> A tile L2 reuse
    dim3 scatGrid((N_EDGES + 7) / 8, R_REL);
    dim3 tpBlock(32, 8);

    const int r0Blocks = (int)(((size_t)N_NODES * DPAD0 + 1023) / 1024);
    const int rhBlocks = (int)(((size_t)N_NODES * DPADH + 1023) / 1024);

    // layer 0: X (N x 162) -> bufA
    transpose_kernel<<<dim3(DPAD0 / 32, 4, NBLK), tpBlock>>>(root0, W0, IN_DIM, DPAD0);
    round_kernel<IN_DIM, DPAD0, false><<<r0Blocks, 1024>>>(X);
    gemm_mma_kernel<<<gemmGrid, 256, GEMM_SMEM>>>(DPAD0, b0, bufA);
    scatter_kernel<<<scatGrid, 256>>>(e[0], e[1], e[2], e[3], e[4], bufA);

    // layer 1: bufA -> bufB (relu folded into round pass)
    transpose_kernel<<<dim3(DPADH / 32, 4, NBLK), tpBlock>>>(rootl, Wl, HID, DPADH);
    round_kernel<HID, DPADH, true><<<rhBlocks, 1024>>>(bufA);
    gemm_mma_kernel<<<gemmGrid, 256, GEMM_SMEM>>>(DPADH, bl, bufB);
    scatter_kernel<<<scatGrid, 256>>>(e[0], e[1], e[2], e[3], e[4], bufB);

    // layer 2: bufB -> bufA
    transpose_kernel<<<dim3(DPADH / 32, 4, NBLK), tpBlock>>>(rootl + (size_t)HID * HID,
                                                             Wl + (size_t)R_REL * HID * HID,
                                                             HID, DPADH);
    round_kernel<HID, DPADH, true><<<rhBlocks, 1024>>>(bufB);
    gemm_mma_kernel<<<gemmGrid, 256, GEMM_SMEM>>>(DPADH, bl + HID, bufA);
    scatter_kernel<<<scatGrid, 256>>>(e[0], e[1], e[2], e[3], e[4], bufA);

    // readout (with ReLU) + MLP head
    readout_kernel<<<N_GRAPH, HID>>>(bufA, batch);
    mlp_kernel<<<N_GRAPH, HID>>>(Wc1, bc1, Wc2, bc2, Wc3, bc3, out);
}

// round 15
// speedup vs baseline: 1.9070x; 1.3071x over previous
#include <cuda_runtime.h>
#include <cstdint>
#include <cstddef>

#define N_NODES 100000
#define N_EDGES 120000
#define N_GRAPH 256
#define IN_DIM  162
#define HID     128
#define R_REL   5
#define NBLK    6            // root + 5 relations
#define DPAD0   192          // IN_DIM padded to 32
#define DPADH   128
#define PADK    36           // smem row stride (floats): conflict-free frag loads
#define NCH     ((N_NODES + 1023) / 1024)   // 98 scan chunks

// ---------------- scratch (static __device__, no allocation) ----------------
__device__ float g_bufA[(size_t)N_NODES * HID];        // final layer output (fp32, relu)
__device__ float g_S[(size_t)N_NODES * HID];           // self term + bias
__device__ float g_M[(size_t)R_REL * N_NODES * HID];   // per-relation messages
__device__ float g_Ar[(size_t)N_NODES * DPAD0];        // pre-rounded padded A
__device__ float g_Bt[(size_t)NBLK * HID * DPAD0];     // transposed pre-rounded weights
__device__ int   g_cnt[R_REL * N_NODES];               // in-degree by (r, dst)
__device__ int   g_bsum[R_REL * NCH];
__device__ int   g_bscan[R_REL * NCH];
__device__ int   g_rowptr[R_REL * (N_NODES + 1)];      // CSR by dst
__device__ int   g_cur[R_REL * N_NODES];
__device__ int   g_esrc[(size_t)R_REL * N_EDGES];      // src ids, dst-sorted
__device__ float g_read[N_GRAPH * HID];

// ---------------- helpers ----------------
__device__ __forceinline__ uint32_t f2tf(float f) {
    uint32_t u;
    asm("cvt.rna.tf32.f32 %0, %1;" : "=r"(u) : "f"(f));
    return u;
}
__device__ __forceinline__ uint32_t smem_u32(const void* p) {
    uint32_t a;
    asm("{ .reg .u64 t; cvta.to.shared.u64 t, %1; cvt.u32.u64 %0, t; }" : "=r"(a) : "l"(p));
    return a;
}
__device__ __forceinline__ void cp_async16(uint32_t dst, const void* src, bool valid) {
    int sz = valid ? 16 : 0;
    asm volatile("cp.async.cg.shared.global [%0], [%1], 16, %2;"
                 :: "r"(dst), "l"(src), "r"(sz));
}
#define CP_COMMIT() asm volatile("cp.async.commit_group;" ::: "memory")
#define CP_WAIT(n)  asm volatile("cp.async.wait_group %0;" :: "n"(n) : "memory")

// ---------------- setup kernels ----------------
__global__ void zero_cnt_kernel() {
    int i = blockIdx.x * blockDim.x + threadIdx.x;
    if (i < R_REL * N_NODES) g_cnt[i] = 0;
}
__global__ void count_kernel(const int* __restrict__ e1, const int* __restrict__ e2,
                             const int* __restrict__ e3, const int* __restrict__ e4,
                             const int* __restrict__ e5) {
    int r = blockIdx.y;
    const int* eis[R_REL] = {e1, e2, e3, e4, e5};
    const int* ei = eis[r];
    int e = blockIdx.x * blockDim.x + threadIdx.x;
    if (e < N_EDGES) atomicAdd(&g_cnt[r * N_NODES + ei[N_EDGES + e]], 1);
}

// scan phase 1: per-1024-chunk sums
__global__ __launch_bounds__(256) void blocksum_kernel() {
    int r = blockIdx.y, b = blockIdx.x, t = threadIdx.x;
    int s = 0;
#pragma unroll
    for (int k = 0; k < 4; k++) {
        int i = b * 1024 + k * 256 + t;
        if (i < N_NODES) s += g_cnt[r * N_NODES + i];
    }
#pragma unroll
    for (int o = 16; o > 0; o >>= 1) s += __shfl_down_sync(~0u, s, o);
    __shared__ int ws[8];
    if ((t & 31) == 0) ws[t >> 5] = s;
    __syncthreads();
    if (t == 0) {
        int tot = 0;
#pragma unroll
        for (int w = 0; w < 8; w++) tot += ws[w];
        g_bsum[r * NCH + b] = tot;
    }
}
// scan phase 2: serial scan of 98 chunk sums per relation (trivial)
__global__ void scanb_kernel() {
    int r = blockIdx.x;
    if (threadIdx.x == 0) {
        int s = 0;
        for (int b = 0; b < NCH; b++) {
            int v = g_bsum[r * NCH + b];
            g_bscan[r * NCH + b] = s;
            s += v;
        }
    }
}
// scan phase 3: block-local exclusive scan + chunk offset -> rowptr, cur
__global__ __launch_bounds__(1024) void rowptr_kernel() {
    int r = blockIdx.y, b = blockIdx.x, t = threadIdx.x;
    int lane = t & 31, w = t >> 5;
    int i = b * 1024 + t;
    int v = (i < N_NODES) ? g_cnt[r * N_NODES + i] : 0;
    int x = v;
#pragma unroll
    for (int o = 1; o < 32; o <<= 1) {
        int y = __shfl_up_sync(~0u, x, o);
        if (lane >= o) x += y;
    }
    __shared__ int ws[32];
    if (lane == 31) ws[w] = x;
    __syncthreads();
    if (w == 0) {
        int s = ws[lane];
#pragma unroll
        for (int o = 1; o < 32; o <<= 1) {
            int y = __shfl_up_sync(~0u, s, o);
            if (lane >= o) s += y;
        }
        ws[lane] = s;
    }
    __syncthreads();
    int excl = g_bscan[r * NCH + b] + (w > 0 ? ws[w - 1] : 0) + x - v;
    if (i < N_NODES) {
        g_rowptr[r * (N_NODES + 1) + i] = excl;
        g_cur[r * N_NODES + i] = excl;
    }
    if (i == N_NODES) g_rowptr[r * (N_NODES + 1) + N_NODES] = excl;
}
__global__ void place_kernel(const int* __restrict__ e1, const int* __restrict__ e2,
                             const int* __restrict__ e3, const int* __restrict__ e4,
                             const int* __restrict__ e5) {
    int r = blockIdx.y;
    const int* eis[R_REL] = {e1, e2, e3, e4, e5};
    const int* ei = eis[r];
    int e = blockIdx.x * blockDim.x + threadIdx.x;
    if (e < N_EDGES) {
        int src = ei[e], dst = ei[N_EDGES + e];
        int pos = atomicAdd(&g_cur[r * N_NODES + dst], 1);
        g_esrc[(size_t)r * N_EDGES + pos] = src;
    }
}

// ---------------- layer-0 A pre-pass: pad + tf32 round X into g_Ar ----------------
__global__ void round0_kernel(const float* __restrict__ in) {
    size_t i = (size_t)blockIdx.x * blockDim.x + threadIdx.x;
    if (i >= (size_t)N_NODES * DPAD0) return;
    int row = (int)(i / DPAD0), col = (int)(i % DPAD0);
    float v = (col < IN_DIM) ? in[(size_t)row * IN_DIM + col] : 0.0f;
    ((uint32_t*)g_Ar)[i] = f2tf(v);
}

// ---------------- weight transpose + round: g_Bt[c][j][k] = tf32(src_c[k][j]) ----------------
__global__ void transpose_kernel(const float* __restrict__ root, const float* __restrict__ W,
                                 int Din, int Dpad) {
    __shared__ float tile[32][33];
    int c = blockIdx.z;
    const float* src = (c == 0) ? root : (W + (size_t)(c - 1) * Din * HID);
    int kt = blockIdx.x * 32, jt = blockIdx.y * 32;
    int tx = threadIdx.x, ty = threadIdx.y;  // 32 x 8
#pragma unroll
    for (int i = 0; i < 4; i++) {
        int k = kt + ty + i * 8, j = jt + tx;
        tile[ty + i * 8][tx] = (k < Din) ? src[(size_t)k * HID + j] : 0.0f;
    }
    __syncthreads();
#pragma unroll
    for (int i = 0; i < 4; i++) {
        int j = jt + ty + i * 8, k = kt + tx;
        ((uint32_t*)g_Bt)[((size_t)c * HID + j) * Dpad + k] = f2tf(tile[tx][ty + i * 8]);
    }
}

// ---------------- tf32 mma GEMM, cp.async 3-stage pipeline ----------------
#define STAGE_BYTES  36864
#define STAGE_FLOATS 9216
#define GEMM_SMEM    (3 * STAGE_BYTES)

__global__ __launch_bounds__(256, 2)
void gemm_mma_kernel(int Dpad, const float* __restrict__ bias,
                     float* __restrict__ outSelf) {
    extern __shared__ float sm[];
    const uint32_t smemU = smem_u32(sm);

    const int c = blockIdx.x;              // 0..5 (fast dim -> A tile L2 reuse)
    const int rowBase = blockIdx.y * 128;
    const int t = threadIdx.x;
    const int wid = t >> 5, lane = t & 31;
    const int warpM = wid >> 2;            // 0..1 (64 rows each)
    const int warpN = wid & 3;             // 0..3 (32 cols each)
    const int lr = lane >> 2;              // 0..7
    const int lc = lane & 3;               // 0..3

    const float* Aar = g_Ar;
    const float* Bt = g_Bt + (size_t)c * HID * Dpad;
    const int nK = Dpad >> 5;

    float cacc[4][4][4];
#pragma unroll
    for (int mt = 0; mt < 4; mt++)
#pragma unroll
        for (int nt = 0; nt < 4; nt++)
#pragma unroll
            for (int q = 0; q < 4; q++) cacc[mt][nt][q] = 0.0f;

#define PREFETCH(I) do {                                                          \
        const int k0_ = (I) * 32;                                                 \
        const uint32_t sA = smemU + ((I) % 3) * STAGE_BYTES;                      \
        const uint32_t sB = sA + STAGE_BYTES / 2;                                 \
        _Pragma("unroll")                                                         \
        for (int p = 0; p < 4; p++) {                                             \
            int ch = p * 256 + t;                                                 \
            int row = ch >> 3, seg = ch & 7;                                      \
            const float* srcA = Aar + (size_t)(rowBase + row) * Dpad + k0_ + seg * 4; \
            cp_async16(sA + row * 144 + seg * 16, srcA, (rowBase + row) < N_NODES);   \
            const float* srcB = Bt + (size_t)row * Dpad + k0_ + seg * 4;          \
            cp_async16(sB + row * 144 + seg * 16, srcB, true);                    \
        }                                                                         \
    } while (0)

#define COMPUTE(S) do {                                                           \
        const float* Ab = sm + (S) * STAGE_FLOATS + (warpM * 64 + lr) * PADK + lc;\
        const float* Bb = sm + (S) * STAGE_FLOATS + STAGE_FLOATS / 2              \
                          + (warpN * 32 + lr) * PADK + lc;                        \
        _Pragma("unroll")                                                         \
        for (int ks = 0; ks < 4; ks++) {                                          \
            const int k0_ = ks * 8;                                               \
            uint32_t afr[4][4], bfr[4][2];                                        \
            _Pragma("unroll")                                                     \
            for (int mt = 0; mt < 4; mt++) {                                      \
                const float* pa = Ab + mt * 16 * PADK + k0_;                      \
                afr[mt][0] = *(const uint32_t*)(pa);                              \
                afr[mt][1] = *(const uint32_t*)(pa + 8 * PADK);                   \
                afr[mt][2] = *(const uint32_t*)(pa + 4);                          \
                afr[mt][3] = *(const uint32_t*)(pa + 8 * PADK + 4);               \
            }                                                                     \
            _Pragma("unroll")                                                     \
            for (int nt = 0; nt < 4; nt++) {                                      \
                const float* pb = Bb + nt * 8 * PADK + k0_;                       \
                bfr[nt][0] = *(const uint32_t*)(pb);                              \
                bfr[nt][1] = *(const uint32_t*)(pb + 4);                          \
            }                                                                     \
            _Pragma("unroll")                                                     \
            for (int mt = 0; mt < 4; mt++)                                        \
                _Pragma("unroll")                                                 \
                for (int nt = 0; nt < 4; nt++) {                                  \
                    asm volatile(                                                 \
                        "mma.sync.aligned.m16n8k8.row.col.f32.tf32.tf32.f32 "     \
                        "{%0,%1,%2,%3}, {%4,%5,%6,%7}, {%8,%9}, {%0,%1,%2,%3};"   \
                        : "+f"(cacc[mt][nt][0]), "+f"(cacc[mt][nt][1]),           \
                          "+f"(cacc[mt][nt][2]), "+f"(cacc[mt][nt][3])            \
                        : "r"(afr[mt][0]), "r"(afr[mt][1]),                       \
                          "r"(afr[mt][2]), "r"(afr[mt][3]),                       \
                          "r"(bfr[nt][0]), "r"(bfr[nt][1]));                      \
                }                                                                 \
        }                                                                         \
    } while (0)

    PREFETCH(0); CP_COMMIT();
    PREFETCH(1); CP_COMMIT();

    int s = 0;
    for (int i = 0; i < nK; i++) {
        if (i + 2 < nK) { PREFETCH(i + 2); CP_COMMIT(); CP_WAIT(2); }
        else if (i + 1 < nK) { CP_WAIT(1); }
        else { CP_WAIT(0); }
        __syncthreads();
        COMPUTE(s);
        __syncthreads();
        if (++s == 3) s = 0;
    }

    // epilogue: direct stores (c-frag m16n8: c0/c1 row=lr col=2lc; c2/c3 row+8)
#pragma unroll
    for (int mt = 0; mt < 4; mt++) {
#pragma unroll
        for (int half = 0; half < 2; half++) {
            int gr = rowBase + warpM * 64 + mt * 16 + lr + half * 8;
            if (gr < N_NODES) {
                float* dst = (c == 0) ? (outSelf + (size_t)gr * HID)
                                      : (g_M + ((size_t)(c - 1) * N_NODES + gr) * HID);
#pragma unroll
                for (int nt = 0; nt < 4; nt++) {
                    int col = warpN * 32 + nt * 8 + lc * 2;
                    float2 v;
                    v.x = cacc[mt][nt][half * 2 + 0];
                    v.y = cacc[mt][nt][half * 2 + 1];
                    if (c == 0) { v.x += bias[col]; v.y += bias[col + 1]; }
                    *(float2*)(dst + col) = v;
                }
            }
        }
    }
#undef PREFETCH
#undef COMPUTE
}

// ---------------- aggregate: out[n] = relu(S[n] + sum_r mean_e M[r][src_e]) ----------------
// warp per node, lane owns cols [4*lane, 4*lane+4). No atomics.
// FINAL=false: write tf32-rounded to g_Ar (stride DPADH) for next GEMM.
// FINAL=true : write fp32 to g_bufA for readout.
template<bool FINAL>
__global__ __launch_bounds__(256)
void aggregate_kernel() {
    int w = (blockIdx.x * blockDim.x + threadIdx.x) >> 5;
    int lane = threadIdx.x & 31;
    if (w >= N_NODES) return;

    float4 acc = ((const float4*)(g_S + (size_t)w * HID))[lane];
#pragma unroll
    for (int r = 0; r < R_REL; r++) {
        int lo = g_rowptr[r * (N_NODES + 1) + w];
        int hi = g_rowptr[r * (N_NODES + 1) + w + 1];
        if (hi > lo) {
            float inv = 1.0f / (float)(hi - lo);
            float4 s = make_float4(0.f, 0.f, 0.f, 0.f);
            for (int e = lo; e < hi; e++) {
                int src = __ldg(&g_esrc[(size_t)r * N_EDGES + e]);
                const float4 m = ((const float4*)(g_M + ((size_t)r * N_NODES + src) * HID))[lane];
                s.x += m.x; s.y += m.y; s.z += m.z; s.w += m.w;
            }
            acc.x += s.x * inv; acc.y += s.y * inv;
            acc.z += s.z * inv; acc.w += s.w * inv;
        }
    }
    acc.x = fmaxf(acc.x, 0.f); acc.y = fmaxf(acc.y, 0.f);
    acc.z = fmaxf(acc.z, 0.f); acc.w = fmaxf(acc.w, 0.f);

    if (FINAL) {
        ((float4*)(g_bufA + (size_t)w * HID))[lane] = acc;
    } else {
        uint4 u = make_uint4(f2tf(acc.x), f2tf(acc.y), f2tf(acc.z), f2tf(acc.w));
        ((uint4*)(g_Ar + (size_t)w * DPADH))[lane] = u;
    }
}

// ---------------- graph readout (batch sorted; input already relu'd) ----------------
__device__ __forceinline__ int lower_bound_dev(const int* a, int n, int key) {
    int lo = 0, hi = n;
    while (lo < hi) {
        int mid = (lo + hi) >> 1;
        if (a[mid] < key) lo = mid + 1; else hi = mid;
    }
    return lo;
}
__global__ void readout_kernel(const float* __restrict__ h, const int* __restrict__ batch) {
    int g = blockIdx.x;
    int j = threadIdx.x;  // 128
    int lo = lower_bound_dev(batch, N_NODES, g);
    int hi = lower_bound_dev(batch, N_NODES, g + 1);
    float s = 0.0f;
    for (int n = lo; n < hi; n++) s += h[(size_t)n * HID + j];
    int c = hi - lo;
    g_read[g * HID + j] = s / (float)(c > 0 ? c : 1);
}

// ---------------- fused MLP head ----------------
__global__ void mlp_kernel(const float* __restrict__ Wc1, const float* __restrict__ bc1,
                           const float* __restrict__ Wc2, const float* __restrict__ bc2,
                           const float* __restrict__ Wc3, const float* __restrict__ bc3,
                           float* __restrict__ out) {
    int g = blockIdx.x;
    int j = threadIdx.x;  // 128
    __shared__ float row[HID];
    __shared__ float h1[HID];
    __shared__ float h2[HID];

    row[j] = g_read[g * HID + j];
    __syncthreads();

    float acc = bc1[j];
    for (int f = 0; f < HID; f++) acc = fmaf(row[f], Wc1[f * HID + j], acc);
    h1[j] = fmaxf(acc, 0.f);
    __syncthreads();

    acc = bc2[j];
    for (int f = 0; f < HID; f++) acc = fmaf(h1[f], Wc2[f * HID + j], acc);
    h2[j] = fmaxf(acc, 0.f) * Wc3[j];
    __syncthreads();

    for (int s = 64; s > 0; s >>= 1) {
        if (j < s) h2[j] += h2[j + s];
        __syncthreads();
    }
    if (j == 0) out[g] = h2[0] + bc3[0];
}

// ---------------- launch ----------------
extern "C" void kernel_launch(void* const* d_in, const int* in_sizes, int n_in,
                              void* d_out, int out_size) {
    const float* X = (const float*)d_in[0];
    const int* e[R_REL];
    const int* batch;
    if (in_sizes[1] == 2 * N_EDGES) {
        for (int r = 0; r < R_REL; r++) e[r] = (const int*)d_in[1 + r];
        batch = (const int*)d_in[6];
    } else {
        batch = (const int*)d_in[1];
        for (int r = 0; r < R_REL; r++) e[r] = (const int*)d_in[2 + r];
    }
    const float* W0    = (const float*)d_in[7];
    const float* root0 = (const float*)d_in[8];
    const float* b0    = (const float*)d_in[9];
    const float* Wl    = (const float*)d_in[10];
    const float* rootl = (const float*)d_in[11];
    const float* bl    = (const float*)d_in[12];
    const float* Wc1   = (const float*)d_in[13];
    const float* bc1   = (const float*)d_in[14];
    const float* Wc2   = (const float*)d_in[15];
    const float* bc2   = (const float*)d_in[16];
    const float* Wc3   = (const float*)d_in[17];
    const float* bc3   = (const float*)d_in[18];
    float*       out   = (float*)d_out;

    float* bufA; cudaGetSymbolAddress((void**)&bufA, g_bufA);
    float* bufS; cudaGetSymbolAddress((void**)&bufS, g_S);

    cudaFuncSetAttribute(gemm_mma_kernel, cudaFuncAttributeMaxDynamicSharedMemorySize, GEMM_SMEM);

    const int gemmRows = (N_NODES + 127) / 128;  // 782
    dim3 gemmGrid(NBLK, gemmRows);
    dim3 tpBlock(32, 8);
    const int r0Blocks = (int)(((size_t)N_NODES * DPAD0 + 1023) / 1024);
    const int aggBlocks = (N_NODES * 32 + 255) / 256;   // warp per node
    dim3 edgeGrid((N_EDGES + 255) / 256, R_REL);

    // --- layer 0 GEMM first (capture slot), CSR setup overlapped after ---
    transpose_kernel<<<dim3(DPAD0 / 32, 4, NBLK), tpBlock>>>(root0, W0, IN_DIM, DPAD0);
    round0_kernel<<<r0Blocks, 1024>>>(X);
    zero_cnt_kernel<<<(R_REL * N_NODES + 255) / 256, 256>>>();
    gemm_mma_kernel<<<gemmGrid, 256, GEMM_SMEM>>>(DPAD0, b0, bufS);

    // dst-CSR: counts -> 3-phase scan -> placement
    count_kernel<<<edgeGrid, 256>>>(e[0], e[1], e[2], e[3], e[4]);
    blocksum_kernel<<<dim3(NCH, R_REL), 256>>>();
    scanb_kernel<<<R_REL, 32>>>();
    rowptr_kernel<<<dim3(NCH, R_REL), 1024>>>();
    place_kernel<<<edgeGrid, 256>>>(e[0], e[1], e[2], e[3], e[4]);

    // layer 0 aggregate -> g_Ar (rounded, stride DPADH)
    aggregate_kernel<false><<<aggBlocks, 256>>>();

    // layer 1
    transpose_kernel<<<dim3(DPADH / 32, 4, NBLK), tpBlock>>>(rootl, Wl, HID, DPADH);
    gemm_mma_kernel<<<gemmGrid, 256, GEMM_SMEM>>>(DPADH, bl, bufS);
    aggregate_kernel<false><<<aggBlocks, 256>>>();

    // layer 2
    transpose_kernel<<<dim3(DPADH / 32, 4, NBLK), tpBlock>>>(rootl + (size_t)HID * HID,
                                                             Wl + (size_t)R_REL * HID * HID,
                                                             HID, DPADH);
    gemm_mma_kernel<<<gemmGrid, 256, GEMM_SMEM>>>(DPADH, bl + HID, bufS);
    aggregate_kernel<true><<<aggBlocks, 256>>>();

    // readout + MLP head
    readout_kernel<<<N_GRAPH, HID>>>(bufA, batch);
    mlp_kernel<<<N_GRAPH, HID>>>(Wc1, bc1, Wc2, bc2, Wc3, bc3, out);
}

// round 16
// speedup vs baseline: 2.4372x; 1.2780x over previous
#include <cuda_runtime.h>
#include <cuda_fp16.h>
#include <cstdint>
#include <cstddef>

#define N_NODES 100000
#define N_EDGES 120000
#define N_GRAPH 256
#define IN_DIM  162
#define HID     128
#define R_REL   5
#define NBLK    6            // root + 5 relations
#define DPAD0   192          // IN_DIM padded to 64
#define DPADH   128
#define NCH     ((N_NODES + 1023) / 1024)   // 98 scan chunks

// ---------------- scratch (static __device__, no allocation) ----------------
__device__ float  g_bufA[(size_t)N_NODES * HID];        // final layer output (fp32, relu)
__device__ float  g_S[(size_t)N_NODES * HID];           // self term + bias
__device__ float  g_M[(size_t)R_REL * N_NODES * HID];   // per-relation messages
__device__ __half g_Ar[(size_t)N_NODES * DPAD0];        // fp16 padded A
__device__ __half g_Bt[(size_t)NBLK * HID * DPAD0];     // transposed fp16 weights (K-major)
__device__ int    g_cnt[R_REL * N_NODES];               // in-degree by (r, dst)
__device__ int    g_bsum[R_REL * NCH];
__device__ int    g_bscan[R_REL * NCH];
__device__ int    g_rowptr[R_REL * (N_NODES + 1)];      // CSR by dst
__device__ int    g_cur[R_REL * N_NODES];
__device__ int    g_esrc[(size_t)R_REL * N_EDGES];      // src ids, dst-sorted
__device__ float  g_read[N_GRAPH * HID];

// ---------------- helpers ----------------
__device__ __forceinline__ uint32_t smem_u32(const void* p) {
    uint32_t a;
    asm("{ .reg .u64 t; cvta.to.shared.u64 t, %1; cvt.u32.u64 %0, t; }" : "=r"(a) : "l"(p));
    return a;
}
__device__ __forceinline__ void cp_async16(uint32_t dst, const void* src, bool valid) {
    int sz = valid ? 16 : 0;
    asm volatile("cp.async.cg.shared.global [%0], [%1], 16, %2;"
                 :: "r"(dst), "l"(src), "r"(sz));
}
#define CP_COMMIT() asm volatile("cp.async.commit_group;" ::: "memory")
#define CP_WAIT(n)  asm volatile("cp.async.wait_group %0;" :: "n"(n) : "memory")

// ---------------- setup kernels ----------------
__global__ void zero_cnt_kernel() {
    int i = blockIdx.x * blockDim.x + threadIdx.x;
    if (i < R_REL * N_NODES) g_cnt[i] = 0;
}
__global__ void count_kernel(const int* __restrict__ e1, const int* __restrict__ e2,
                             const int* __restrict__ e3, const int* __restrict__ e4,
                             const int* __restrict__ e5) {
    int r = blockIdx.y;
    const int* eis[R_REL] = {e1, e2, e3, e4, e5};
    const int* ei = eis[r];
    int e = blockIdx.x * blockDim.x + threadIdx.x;
    if (e < N_EDGES) atomicAdd(&g_cnt[r * N_NODES + ei[N_EDGES + e]], 1);
}

// scan phase 1: per-1024-chunk sums
__global__ __launch_bounds__(256) void blocksum_kernel() {
    int r = blockIdx.y, b = blockIdx.x, t = threadIdx.x;
    int s = 0;
#pragma unroll
    for (int k = 0; k < 4; k++) {
        int i = b * 1024 + k * 256 + t;
        if (i < N_NODES) s += g_cnt[r * N_NODES + i];
    }
#pragma unroll
    for (int o = 16; o > 0; o >>= 1) s += __shfl_down_sync(~0u, s, o);
    __shared__ int ws[8];
    if ((t & 31) == 0) ws[t >> 5] = s;
    __syncthreads();
    if (t == 0) {
        int tot = 0;
#pragma unroll
        for (int w = 0; w < 8; w++) tot += ws[w];
        g_bsum[r * NCH + b] = tot;
    }
}
__global__ void scanb_kernel() {
    int r = blockIdx.x;
    if (threadIdx.x == 0) {
        int s = 0;
        for (int b = 0; b < NCH; b++) {
            int v = g_bsum[r * NCH + b];
            g_bscan[r * NCH + b] = s;
            s += v;
        }
    }
}
__global__ __launch_bounds__(1024) void rowptr_kernel() {
    int r = blockIdx.y, b = blockIdx.x, t = threadIdx.x;
    int lane = t & 31, w = t >> 5;
    int i = b * 1024 + t;
    int v = (i < N_NODES) ? g_cnt[r * N_NODES + i] : 0;
    int x = v;
#pragma unroll
    for (int o = 1; o < 32; o <<= 1) {
        int y = __shfl_up_sync(~0u, x, o);
        if (lane >= o) x += y;
    }
    __shared__ int ws[32];
    if (lane == 31) ws[w] = x;
    __syncthreads();
    if (w == 0) {
        int s = ws[lane];
#pragma unroll
        for (int o = 1; o < 32; o <<= 1) {
            int y = __shfl_up_sync(~0u, s, o);
            if (lane >= o) s += y;
        }
        ws[lane] = s;
    }
    __syncthreads();
    int excl = g_bscan[r * NCH + b] + (w > 0 ? ws[w - 1] : 0) + x - v;
    if (i < N_NODES) {
        g_rowptr[r * (N_NODES + 1) + i] = excl;
        g_cur[r * N_NODES + i] = excl;
    }
    if (i == N_NODES) g_rowptr[r * (N_NODES + 1) + N_NODES] = excl;
}
__global__ void place_kernel(const int* __restrict__ e1, const int* __restrict__ e2,
                             const int* __restrict__ e3, const int* __restrict__ e4,
                             const int* __restrict__ e5) {
    int r = blockIdx.y;
    const int* eis[R_REL] = {e1, e2, e3, e4, e5};
    const int* ei = eis[r];
    int e = blockIdx.x * blockDim.x + threadIdx.x;
    if (e < N_EDGES) {
        int src = ei[e], dst = ei[N_EDGES + e];
        int pos = atomicAdd(&g_cur[r * N_NODES + dst], 1);
        g_esrc[(size_t)r * N_EDGES + pos] = src;
    }
}

// ---------------- layer-0 A pre-pass: pad + fp16 X into g_Ar ----------------
__global__ void round0_kernel(const float* __restrict__ in) {
    size_t i = (size_t)blockIdx.x * blockDim.x + threadIdx.x;
    if (i >= (size_t)N_NODES * DPAD0) return;
    int row = (int)(i / DPAD0), col = (int)(i % DPAD0);
    float v = (col < IN_DIM) ? in[(size_t)row * IN_DIM + col] : 0.0f;
    g_Ar[i] = __float2half_rn(v);
}

// ---------------- weight transpose: g_Bt[c][j][k] = fp16(src_c[k][j]) ----------------
__global__ void transpose_kernel(const float* __restrict__ root, const float* __restrict__ W,
                                 int Din, int Dpad) {
    __shared__ float tile[32][33];
    int c = blockIdx.z;
    const float* src = (c == 0) ? root : (W + (size_t)(c - 1) * Din * HID);
    int kt = blockIdx.x * 32, jt = blockIdx.y * 32;
    int tx = threadIdx.x, ty = threadIdx.y;  // 32 x 8
#pragma unroll
    for (int i = 0; i < 4; i++) {
        int k = kt + ty + i * 8, j = jt + tx;
        tile[ty + i * 8][tx] = (k < Din) ? src[(size_t)k * HID + j] : 0.0f;
    }
    __syncthreads();
#pragma unroll
    for (int i = 0; i < 4; i++) {
        int j = jt + ty + i * 8, k = kt + tx;
        g_Bt[((size_t)c * HID + j) * Dpad + k] = __float2half_rn(tile[tx][ty + i * 8]);
    }
}

// ---------------- fp16 mma GEMM (m16n8k16), cp.async 3-stage pipeline ----------------
// BK=64 halves per chunk. Row stride 144B (72 halves: 64 data + 8 pad) ->
// frag LDS bank = (4*lr + lc) mod 32, conflict-free.
#define ROWB         144
#define HALF_STAGE   (128 * ROWB)           // 18432 B (A or B part)
#define STAGE_BYTES  (2 * HALF_STAGE)       // 36864 B
#define GEMM_SMEM    (3 * STAGE_BYTES)      // 110592 B

__global__ __launch_bounds__(256, 2)
void gemm_mma_kernel(int Dpad, const float* __restrict__ bias,
                     float* __restrict__ outSelf) {
    extern __shared__ char sm[];
    const uint32_t smemU = smem_u32(sm);

    const int c = blockIdx.x;              // 0..5 (fast dim -> A tile L2 reuse)
    const int rowBase = blockIdx.y * 128;
    const int t = threadIdx.x;
    const int wid = t >> 5, lane = t & 31;
    const int warpM = wid >> 2;            // 0..1 (64 rows each)
    const int warpN = wid & 3;             // 0..3 (32 cols each)
    const int lr = lane >> 2;              // 0..7
    const int lc = lane & 3;               // 0..3

    const __half* Aar = g_Ar;
    const __half* Bt = g_Bt + (size_t)c * HID * Dpad;
    const int nK = Dpad >> 6;              // chunks of 64

    float cacc[4][4][4];
#pragma unroll
    for (int mt = 0; mt < 4; mt++)
#pragma unroll
        for (int nt = 0; nt < 4; nt++)
#pragma unroll
            for (int q = 0; q < 4; q++) cacc[mt][nt][q] = 0.0f;

#define PREFETCH(I) do {                                                          \
        const int k0_ = (I) * 64;                                                 \
        const uint32_t sA = smemU + ((I) % 3) * STAGE_BYTES;                      \
        const uint32_t sB = sA + HALF_STAGE;                                      \
        _Pragma("unroll")                                                         \
        for (int p = 0; p < 4; p++) {                                             \
            int ch = p * 256 + t;                                                 \
            int row = ch >> 3, seg = ch & 7;                                      \
            const __half* srcA = Aar + (size_t)(rowBase + row) * Dpad + k0_ + seg * 8; \
            cp_async16(sA + row * ROWB + seg * 16, srcA, (rowBase + row) < N_NODES);   \
            const __half* srcB = Bt + (size_t)row * Dpad + k0_ + seg * 8;         \
            cp_async16(sB + row * ROWB + seg * 16, srcB, true);                   \
        }                                                                         \
    } while (0)

#define COMPUTE(S) do {                                                           \
        const char* Ab = sm + (S) * STAGE_BYTES + (warpM * 64 + lr) * ROWB + lc * 4;   \
        const char* Bb = sm + (S) * STAGE_BYTES + HALF_STAGE                      \
                          + (warpN * 32 + lr) * ROWB + lc * 4;                    \
        _Pragma("unroll")                                                         \
        for (int ks = 0; ks < 4; ks++) {                                          \
            const int kb_ = ks * 32;   /* 16 halves = 32 B */                     \
            uint32_t afr[4][4], bfr[4][2];                                        \
            _Pragma("unroll")                                                     \
            for (int mt = 0; mt < 4; mt++) {                                      \
                const char* pa = Ab + mt * 16 * ROWB + kb_;                       \
                afr[mt][0] = *(const uint32_t*)(pa);                              \
                afr[mt][1] = *(const uint32_t*)(pa + 8 * ROWB);                   \
                afr[mt][2] = *(const uint32_t*)(pa + 16);                         \
                afr[mt][3] = *(const uint32_t*)(pa + 8 * ROWB + 16);              \
            }                                                                     \
            _Pragma("unroll")                                                     \
            for (int nt = 0; nt < 4; nt++) {                                      \
                const char* pb = Bb + nt * 8 * ROWB + kb_;                        \
                bfr[nt][0] = *(const uint32_t*)(pb);                              \
                bfr[nt][1] = *(const uint32_t*)(pb + 16);                         \
            }                                                                     \
            _Pragma("unroll")                                                     \
            for (int mt = 0; mt < 4; mt++)                                        \
                _Pragma("unroll")                                                 \
                for (int nt = 0; nt < 4; nt++) {                                  \
                    asm volatile(                                                 \
                        "mma.sync.aligned.m16n8k16.row.col.f32.f16.f16.f32 "      \
                        "{%0,%1,%2,%3}, {%4,%5,%6,%7}, {%8,%9}, {%0,%1,%2,%3};"   \
                        : "+f"(cacc[mt][nt][0]), "+f"(cacc[mt][nt][1]),           \
                          "+f"(cacc[mt][nt][2]), "+f"(cacc[mt][nt][3])            \
                        : "r"(afr[mt][0]), "r"(afr[mt][1]),                       \
                          "r"(afr[mt][2]), "r"(afr[mt][3]),                       \
                          "r"(bfr[nt][0]), "r"(bfr[nt][1]));                      \
                }                                                                 \
        }                                                                         \
    } while (0)

    PREFETCH(0); CP_COMMIT();
    if (nK > 1) { PREFETCH(1); CP_COMMIT(); }

    int s = 0;
    for (int i = 0; i < nK; i++) {
        if (i + 2 < nK) { PREFETCH(i + 2); CP_COMMIT(); CP_WAIT(2); }
        else if (i + 1 < nK) { CP_WAIT(1); }
        else { CP_WAIT(0); }
        __syncthreads();
        COMPUTE(s);
        __syncthreads();
        if (++s == 3) s = 0;
    }

    // epilogue: direct stores (c-frag m16n8: c0/c1 row=lr col=2lc; c2/c3 row+8)
#pragma unroll
    for (int mt = 0; mt < 4; mt++) {
#pragma unroll
        for (int half = 0; half < 2; half++) {
            int gr = rowBase + warpM * 64 + mt * 16 + lr + half * 8;
            if (gr < N_NODES) {
                float* dst = (c == 0) ? (outSelf + (size_t)gr * HID)
                                      : (g_M + ((size_t)(c - 1) * N_NODES + gr) * HID);
#pragma unroll
                for (int nt = 0; nt < 4; nt++) {
                    int col = warpN * 32 + nt * 8 + lc * 2;
                    float2 v;
                    v.x = cacc[mt][nt][half * 2 + 0];
                    v.y = cacc[mt][nt][half * 2 + 1];
                    if (c == 0) { v.x += bias[col]; v.y += bias[col + 1]; }
                    *(float2*)(dst + col) = v;
                }
            }
        }
    }
#undef PREFETCH
#undef COMPUTE
}

// ---------------- aggregate: out[n] = relu(S[n] + sum_r mean_e M[r][src_e]) ----------------
// warp per node, lane owns cols [4*lane, 4*lane+4). No atomics.
template<bool FINAL>
__global__ __launch_bounds__(256)
void aggregate_kernel() {
    int w = (blockIdx.x * blockDim.x + threadIdx.x) >> 5;
    int lane = threadIdx.x & 31;
    if (w >= N_NODES) return;

    float4 acc = ((const float4*)(g_S + (size_t)w * HID))[lane];
#pragma unroll
    for (int r = 0; r < R_REL; r++) {
        int lo = g_rowptr[r * (N_NODES + 1) + w];
        int hi = g_rowptr[r * (N_NODES + 1) + w + 1];
        if (hi > lo) {
            float inv = 1.0f / (float)(hi - lo);
            float4 s = make_float4(0.f, 0.f, 0.f, 0.f);
            for (int e = lo; e < hi; e++) {
                int src = __ldg(&g_esrc[(size_t)r * N_EDGES + e]);
                const float4 m = ((const float4*)(g_M + ((size_t)r * N_NODES + src) * HID))[lane];
                s.x += m.x; s.y += m.y; s.z += m.z; s.w += m.w;
            }
            acc.x += s.x * inv; acc.y += s.y * inv;
            acc.z += s.z * inv; acc.w += s.w * inv;
        }
    }
    acc.x = fmaxf(acc.x, 0.f); acc.y = fmaxf(acc.y, 0.f);
    acc.z = fmaxf(acc.z, 0.f); acc.w = fmaxf(acc.w, 0.f);

    if (FINAL) {
        ((float4*)(g_bufA + (size_t)w * HID))[lane] = acc;
    } else {
        __half2 h0 = __floats2half2_rn(acc.x, acc.y);
        __half2 h1 = __floats2half2_rn(acc.z, acc.w);
        uint2 u = make_uint2(*(uint32_t*)&h0, *(uint32_t*)&h1);
        ((uint2*)(g_Ar + (size_t)w * DPADH))[lane] = u;
    }
}

// ---------------- graph readout (batch sorted; input already relu'd) ----------------
__device__ __forceinline__ int lower_bound_dev(const int* a, int n, int key) {
    int lo = 0, hi = n;
    while (lo < hi) {
        int mid = (lo + hi) >> 1;
        if (a[mid] < key) lo = mid + 1; else hi = mid;
    }
    return lo;
}
__global__ void readout_kernel(const float* __restrict__ h, const int* __restrict__ batch) {
    int g = blockIdx.x;
    int j = threadIdx.x;  // 128
    int lo = lower_bound_dev(batch, N_NODES, g);
    int hi = lower_bound_dev(batch, N_NODES, g + 1);
    float s = 0.0f;
    for (int n = lo; n < hi; n++) s += h[(size_t)n * HID + j];
    int c = hi - lo;
    g_read[g * HID + j] = s / (float)(c > 0 ? c : 1);
}

// ---------------- fused MLP head ----------------
__global__ void mlp_kernel(const float* __restrict__ Wc1, const float* __restrict__ bc1,
                           const float* __restrict__ Wc2, const float* __restrict__ bc2,
                           const float* __restrict__ Wc3, const float* __restrict__ bc3,
                           float* __restrict__ out) {
    int g = blockIdx.x;
    int j = threadIdx.x;  // 128
    __shared__ float row[HID];
    __shared__ float h1[HID];
    __shared__ float h2[HID];

    row[j] = g_read[g * HID + j];
    __syncthreads();

    float acc = bc1[j];
    for (int f = 0; f < HID; f++) acc = fmaf(row[f], Wc1[f * HID + j], acc);
    h1[j] = fmaxf(acc, 0.f);
    __syncthreads();

    acc = bc2[j];
    for (int f = 0; f < HID; f++) acc = fmaf(h1[f], Wc2[f * HID + j], acc);
    h2[j] = fmaxf(acc, 0.f) * Wc3[j];
    __syncthreads();

    for (int s = 64; s > 0; s >>= 1) {
        if (j < s) h2[j] += h2[j + s];
        __syncthreads();
    }
    if (j == 0) out[g] = h2[0] + bc3[0];
}

// ---------------- launch ----------------
extern "C" void kernel_launch(void* const* d_in, const int* in_sizes, int n_in,
                              void* d_out, int out_size) {
    const float* X = (const float*)d_in[0];
    const int* e[R_REL];
    const int* batch;
    if (in_sizes[1] == 2 * N_EDGES) {
        for (int r = 0; r < R_REL; r++) e[r] = (const int*)d_in[1 + r];
        batch = (const int*)d_in[6];
    } else {
        batch = (const int*)d_in[1];
        for (int r = 0; r < R_REL; r++) e[r] = (const int*)d_in[2 + r];
    }
    const float* W0    = (const float*)d_in[7];
    const float* root0 = (const float*)d_in[8];
    const float* b0    = (const float*)d_in[9];
    const float* Wl    = (const float*)d_in[10];
    const float* rootl = (const float*)d_in[11];
    const float* bl    = (const float*)d_in[12];
    const float* Wc1   = (const float*)d_in[13];
    const float* bc1   = (const float*)d_in[14];
    const float* Wc2   = (const float*)d_in[15];
    const float* bc2   = (const float*)d_in[16];
    const float* Wc3   = (const float*)d_in[17];
    const float* bc3   = (const float*)d_in[18];
    float*       out   = (float*)d_out;

    float* bufA; cudaGetSymbolAddress((void**)&bufA, g_bufA);
    float* bufS; cudaGetSymbolAddress((void**)&bufS, g_S);

    cudaFuncSetAttribute(gemm_mma_kernel, cudaFuncAttributeMaxDynamicSharedMemorySize, GEMM_SMEM);

    const int gemmRows = (N_NODES + 127) / 128;  // 782
    dim3 gemmGrid(NBLK, gemmRows);
    dim3 tpBlock(32, 8);
    const int r0Blocks = (int)(((size_t)N_NODES * DPAD0 + 1023) / 1024);
    const int aggBlocks = (N_NODES * 32 + 255) / 256;   // warp per node
    dim3 edgeGrid((N_EDGES + 255) / 256, R_REL);

    // --- layer 0 GEMM first (capture slot), CSR setup after ---
    transpose_kernel<<<dim3(DPAD0 / 32, 4, NBLK), tpBlock>>>(root0, W0, IN_DIM, DPAD0);
    round0_kernel<<<r0Blocks, 1024>>>(X);
    zero_cnt_kernel<<<(R_REL * N_NODES + 255) / 256, 256>>>();
    gemm_mma_kernel<<<gemmGrid, 256, GEMM_SMEM>>>(DPAD0, b0, bufS);

    // dst-CSR: counts -> 3-phase scan -> placement
    count_kernel<<<edgeGrid, 256>>>(e[0], e[1], e[2], e[3], e[4]);
    blocksum_kernel<<<dim3(NCH, R_REL), 256>>>();
    scanb_kernel<<<R_REL, 32>>>();
    rowptr_kernel<<<dim3(NCH, R_REL), 1024>>>();
    place_kernel<<<edgeGrid, 256>>>(e[0], e[1], e[2], e[3], e[4]);

    // layer 0 aggregate -> g_Ar (fp16, stride DPADH)
    aggregate_kernel<false><<<aggBlocks, 256>>>();

    // layer 1
    transpose_kernel<<<dim3(DPADH / 32, 4, NBLK), tpBlock>>>(rootl, Wl, HID, DPADH);
    gemm_mma_kernel<<<gemmGrid, 256, GEMM_SMEM>>>(DPADH, bl, bufS);
    aggregate_kernel<false><<<aggBlocks, 256>>>();

    // layer 2
    transpose_kernel<<<dim3(DPADH / 32, 4, NBLK), tpBlock>>>(rootl + (size_t)HID * HID,
                                                             Wl + (size_t)R_REL * HID * HID,
                                                             HID, DPADH);
    gemm_mma_kernel<<<gemmGrid, 256, GEMM_SMEM>>>(DPADH, bl + HID, bufS);
    aggregate_kernel<true><<<aggBlocks, 256>>>();

    // readout + MLP head
    readout_kernel<<<N_GRAPH, HID>>>(bufA, batch);
    mlp_kernel<<<N_GRAPH, HID>>>(Wc1, bc1, Wc2, bc2, Wc3, bc3, out);
}

// round 17
// speedup vs baseline: 2.5758x; 1.0569x over previous
#include <cuda_runtime.h>
#include <cuda_fp16.h>
#include <cstdint>
#include <cstddef>

#define N_NODES 100000
#define N_EDGES 120000
#define N_GRAPH 256
#define IN_DIM  162
#define HID     128
#define R_REL   5
#define NBLK    6            // root + 5 relations
#define DPAD0   192          // IN_DIM padded to 64
#define DPADH   128
#define NCH     ((N_NODES + 1023) / 1024)   // 98 scan chunks

// ---------------- scratch (static __device__, no allocation) ----------------
__device__ float  g_bufA[(size_t)N_NODES * HID];        // final layer output (fp32, relu)
__device__ float  g_S[(size_t)N_NODES * HID];           // self term + bias (fp32)
__device__ __half g_M[(size_t)R_REL * N_NODES * HID];   // per-relation messages (fp16)
__device__ __half g_Ar[(size_t)N_NODES * DPAD0];        // fp16 padded A
__device__ __half g_Bt[(size_t)NBLK * HID * DPAD0];     // transposed fp16 weights (K-major)
__device__ int    g_cnt[R_REL * N_NODES];               // in-degree by (r, dst)
__device__ int    g_bsum[R_REL * NCH];
__device__ int    g_bscan[R_REL * NCH];
__device__ int    g_rowptr[R_REL * (N_NODES + 1)];      // CSR by dst
__device__ int    g_cur[R_REL * N_NODES];
__device__ int    g_esrc[(size_t)R_REL * N_EDGES];      // src ids, dst-sorted
__device__ float  g_read[N_GRAPH * HID];

// ---------------- helpers ----------------
__device__ __forceinline__ uint32_t smem_u32(const void* p) {
    uint32_t a;
    asm("{ .reg .u64 t; cvta.to.shared.u64 t, %1; cvt.u32.u64 %0, t; }" : "=r"(a) : "l"(p));
    return a;
}
__device__ __forceinline__ void cp_async16(uint32_t dst, const void* src, bool valid) {
    int sz = valid ? 16 : 0;
    asm volatile("cp.async.cg.shared.global [%0], [%1], 16, %2;"
                 :: "r"(dst), "l"(src), "r"(sz));
}
#define CP_COMMIT() asm volatile("cp.async.commit_group;" ::: "memory")
#define CP_WAIT(n)  asm volatile("cp.async.wait_group %0;" :: "n"(n) : "memory")

__device__ __forceinline__ void ldsm_x4(uint32_t& r0, uint32_t& r1, uint32_t& r2, uint32_t& r3,
                                        uint32_t addr) {
    asm volatile("ldmatrix.sync.aligned.m8n8.x4.shared.b16 {%0,%1,%2,%3}, [%4];"
                 : "=r"(r0), "=r"(r1), "=r"(r2), "=r"(r3) : "r"(addr));
}

// ---------------- setup kernels ----------------
__global__ void zero_cnt_kernel() {
    int i = blockIdx.x * blockDim.x + threadIdx.x;
    if (i < R_REL * N_NODES) g_cnt[i] = 0;
}
__global__ void count_kernel(const int* __restrict__ e1, const int* __restrict__ e2,
                             const int* __restrict__ e3, const int* __restrict__ e4,
                             const int* __restrict__ e5) {
    int r = blockIdx.y;
    const int* eis[R_REL] = {e1, e2, e3, e4, e5};
    const int* ei = eis[r];
    int e = blockIdx.x * blockDim.x + threadIdx.x;
    if (e < N_EDGES) atomicAdd(&g_cnt[r * N_NODES + ei[N_EDGES + e]], 1);
}

__global__ __launch_bounds__(256) void blocksum_kernel() {
    int r = blockIdx.y, b = blockIdx.x, t = threadIdx.x;
    int s = 0;
#pragma unroll
    for (int k = 0; k < 4; k++) {
        int i = b * 1024 + k * 256 + t;
        if (i < N_NODES) s += g_cnt[r * N_NODES + i];
    }
#pragma unroll
    for (int o = 16; o > 0; o >>= 1) s += __shfl_down_sync(~0u, s, o);
    __shared__ int ws[8];
    if ((t & 31) == 0) ws[t >> 5] = s;
    __syncthreads();
    if (t == 0) {
        int tot = 0;
#pragma unroll
        for (int w = 0; w < 8; w++) tot += ws[w];
        g_bsum[r * NCH + b] = tot;
    }
}
__global__ void scanb_kernel() {
    int r = blockIdx.x;
    if (threadIdx.x == 0) {
        int s = 0;
        for (int b = 0; b < NCH; b++) {
            int v = g_bsum[r * NCH + b];
            g_bscan[r * NCH + b] = s;
            s += v;
        }
    }
}
__global__ __launch_bounds__(1024) void rowptr_kernel() {
    int r = blockIdx.y, b = blockIdx.x, t = threadIdx.x;
    int lane = t & 31, w = t >> 5;
    int i = b * 1024 + t;
    int v = (i < N_NODES) ? g_cnt[r * N_NODES + i] : 0;
    int x = v;
#pragma unroll
    for (int o = 1; o < 32; o <<= 1) {
        int y = __shfl_up_sync(~0u, x, o);
        if (lane >= o) x += y;
    }
    __shared__ int ws[32];
    if (lane == 31) ws[w] = x;
    __syncthreads();
    if (w == 0) {
        int s = ws[lane];
#pragma unroll
        for (int o = 1; o < 32; o <<= 1) {
            int y = __shfl_up_sync(~0u, s, o);
            if (lane >= o) s += y;
        }
        ws[lane] = s;
    }
    __syncthreads();
    int excl = g_bscan[r * NCH + b] + (w > 0 ? ws[w - 1] : 0) + x - v;
    if (i < N_NODES) {
        g_rowptr[r * (N_NODES + 1) + i] = excl;
        g_cur[r * N_NODES + i] = excl;
    }
    if (i == N_NODES) g_rowptr[r * (N_NODES + 1) + N_NODES] = excl;
}
__global__ void place_kernel(const int* __restrict__ e1, const int* __restrict__ e2,
                             const int* __restrict__ e3, const int* __restrict__ e4,
                             const int* __restrict__ e5) {
    int r = blockIdx.y;
    const int* eis[R_REL] = {e1, e2, e3, e4, e5};
    const int* ei = eis[r];
    int e = blockIdx.x * blockDim.x + threadIdx.x;
    if (e < N_EDGES) {
        int src = ei[e], dst = ei[N_EDGES + e];
        int pos = atomicAdd(&g_cur[r * N_NODES + dst], 1);
        g_esrc[(size_t)r * N_EDGES + pos] = src;
    }
}

// ---------------- layer-0 A pre-pass: pad + fp16 X into g_Ar ----------------
__global__ void round0_kernel(const float* __restrict__ in) {
    size_t i = (size_t)blockIdx.x * blockDim.x + threadIdx.x;
    if (i >= (size_t)N_NODES * DPAD0) return;
    int row = (int)(i / DPAD0), col = (int)(i % DPAD0);
    float v = (col < IN_DIM) ? in[(size_t)row * IN_DIM + col] : 0.0f;
    g_Ar[i] = __float2half_rn(v);
}

// ---------------- weight transpose: g_Bt[c][j][k] = fp16(src_c[k][j]) ----------------
__global__ void transpose_kernel(const float* __restrict__ root, const float* __restrict__ W,
                                 int Din, int Dpad) {
    __shared__ float tile[32][33];
    int c = blockIdx.z;
    const float* src = (c == 0) ? root : (W + (size_t)(c - 1) * Din * HID);
    int kt = blockIdx.x * 32, jt = blockIdx.y * 32;
    int tx = threadIdx.x, ty = threadIdx.y;  // 32 x 8
#pragma unroll
    for (int i = 0; i < 4; i++) {
        int k = kt + ty + i * 8, j = jt + tx;
        tile[ty + i * 8][tx] = (k < Din) ? src[(size_t)k * HID + j] : 0.0f;
    }
    __syncthreads();
#pragma unroll
    for (int i = 0; i < 4; i++) {
        int j = jt + ty + i * 8, k = kt + tx;
        g_Bt[((size_t)c * HID + j) * Dpad + k] = __float2half_rn(tile[tx][ty + i * 8]);
    }
}

// ---------------- fp16 mma GEMM (m16n8k16) + ldmatrix, cp.async 3-stage ----------------
// BK=64 halves/chunk. Row stride 144B (72 halves) -> ldmatrix phases conflict-free
// (row r starts at bank 4r mod 32, bijective over 8 rows).
#define ROWB         144
#define HALF_STAGE   (128 * ROWB)           // 18432 B
#define STAGE_BYTES  (2 * HALF_STAGE)       // 36864 B
#define GEMM_SMEM    (3 * STAGE_BYTES)      // 110592 B

__global__ __launch_bounds__(256, 2)
void gemm_mma_kernel(int Dpad, const float* __restrict__ bias,
                     float* __restrict__ outSelf) {
    extern __shared__ char sm[];
    const uint32_t smemU = smem_u32(sm);

    const int c = blockIdx.x;              // 0..5 (fast dim -> A tile L2 reuse)
    const int rowBase = blockIdx.y * 128;
    const int t = threadIdx.x;
    const int wid = t >> 5, lane = t & 31;
    const int warpM = wid >> 2;            // 0..1 (64 rows each)
    const int warpN = wid & 3;             // 0..3 (32 cols each)
    const int lr = lane >> 2;              // 0..7
    const int lc = lane & 3;               // 0..3

    const __half* Aar = g_Ar;
    const __half* Bt = g_Bt + (size_t)c * HID * Dpad;
    const int nK = Dpad >> 6;              // chunks of 64

    // ldmatrix lane address components
    const int aRow = lane & 15, aSeg = lane >> 4;          // A: 16x16 tile
    const int bMat = lane >> 3, bRow = lane & 7;           // B: 4 n-blocks x 8 rows

    float cacc[4][4][4];
#pragma unroll
    for (int mt = 0; mt < 4; mt++)
#pragma unroll
        for (int nt = 0; nt < 4; nt++)
#pragma unroll
            for (int q = 0; q < 4; q++) cacc[mt][nt][q] = 0.0f;

#define PREFETCH(I) do {                                                          \
        const int k0_ = (I) * 64;                                                 \
        const uint32_t sA = smemU + ((I) % 3) * STAGE_BYTES;                      \
        const uint32_t sB = sA + HALF_STAGE;                                      \
        _Pragma("unroll")                                                         \
        for (int p = 0; p < 4; p++) {                                             \
            int ch = p * 256 + t;                                                 \
            int row = ch >> 3, seg = ch & 7;                                      \
            const __half* srcA = Aar + (size_t)(rowBase + row) * Dpad + k0_ + seg * 8; \
            cp_async16(sA + row * ROWB + seg * 16, srcA, (rowBase + row) < N_NODES);   \
            const __half* srcB = Bt + (size_t)row * Dpad + k0_ + seg * 8;         \
            cp_async16(sB + row * ROWB + seg * 16, srcB, true);                   \
        }                                                                         \
    } while (0)

#define COMPUTE(S) do {                                                           \
        const uint32_t Ab = smemU + (S) * STAGE_BYTES + (warpM * 64 + aRow) * ROWB \
                            + aSeg * 16;                                          \
        const uint32_t Bb = smemU + (S) * STAGE_BYTES + HALF_STAGE                \
                            + (warpN * 32 + bMat * 8 + bRow) * ROWB;              \
        _Pragma("unroll")                                                         \
        for (int ks = 0; ks < 4; ks++) {                                          \
            const int kb_ = ks * 32;   /* 16 halves = 32 B */                     \
            uint32_t afr[4][4], b0[4], b1[4];                                     \
            _Pragma("unroll")                                                     \
            for (int mt = 0; mt < 4; mt++)                                        \
                ldsm_x4(afr[mt][0], afr[mt][1], afr[mt][2], afr[mt][3],           \
                        Ab + mt * 16 * ROWB + kb_);                               \
            ldsm_x4(b0[0], b0[1], b0[2], b0[3], Bb + kb_);                        \
            ldsm_x4(b1[0], b1[1], b1[2], b1[3], Bb + kb_ + 16);                   \
            _Pragma("unroll")                                                     \
            for (int mt = 0; mt < 4; mt++)                                        \
                _Pragma("unroll")                                                 \
                for (int nt = 0; nt < 4; nt++) {                                  \
                    asm volatile(                                                 \
                        "mma.sync.aligned.m16n8k16.row.col.f32.f16.f16.f32 "      \
                        "{%0,%1,%2,%3}, {%4,%5,%6,%7}, {%8,%9}, {%0,%1,%2,%3};"   \
                        : "+f"(cacc[mt][nt][0]), "+f"(cacc[mt][nt][1]),           \
                          "+f"(cacc[mt][nt][2]), "+f"(cacc[mt][nt][3])            \
                        : "r"(afr[mt][0]), "r"(afr[mt][1]),                       \
                          "r"(afr[mt][2]), "r"(afr[mt][3]),                       \
                          "r"(b0[nt]), "r"(b1[nt]));                              \
                }                                                                 \
        }                                                                         \
    } while (0)

    PREFETCH(0); CP_COMMIT();
    if (nK > 1) { PREFETCH(1); CP_COMMIT(); }

    int s = 0;
    for (int i = 0; i < nK; i++) {
        if (i + 2 < nK) { PREFETCH(i + 2); CP_COMMIT(); CP_WAIT(2); }
        else if (i + 1 < nK) { CP_WAIT(1); }
        else { CP_WAIT(0); }
        __syncthreads();
        COMPUTE(s);
        __syncthreads();
        if (++s == 3) s = 0;
    }

    // epilogue: c=0 -> fp32 S (+bias); c>0 -> fp16 M
#pragma unroll
    for (int mt = 0; mt < 4; mt++) {
#pragma unroll
        for (int half = 0; half < 2; half++) {
            int gr = rowBase + warpM * 64 + mt * 16 + lr + half * 8;
            if (gr < N_NODES) {
                if (c == 0) {
                    float* dst = outSelf + (size_t)gr * HID;
#pragma unroll
                    for (int nt = 0; nt < 4; nt++) {
                        int col = warpN * 32 + nt * 8 + lc * 2;
                        float2 v;
                        v.x = cacc[mt][nt][half * 2 + 0] + bias[col];
                        v.y = cacc[mt][nt][half * 2 + 1] + bias[col + 1];
                        *(float2*)(dst + col) = v;
                    }
                } else {
                    __half* dst = g_M + ((size_t)(c - 1) * N_NODES + gr) * HID;
#pragma unroll
                    for (int nt = 0; nt < 4; nt++) {
                        int col = warpN * 32 + nt * 8 + lc * 2;
                        __half2 h = __floats2half2_rn(cacc[mt][nt][half * 2 + 0],
                                                      cacc[mt][nt][half * 2 + 1]);
                        *(__half2*)(dst + col) = h;
                    }
                }
            }
        }
    }
#undef PREFETCH
#undef COMPUTE
}

// ---------------- aggregate: out[n] = relu(S[n] + sum_r mean_e M[r][src_e]) ----------------
// warp per node, lane owns cols [4*lane, 4*lane+4). M is fp16; fp32 accumulate.
template<bool FINAL>
__global__ __launch_bounds__(256)
void aggregate_kernel() {
    int w = (blockIdx.x * blockDim.x + threadIdx.x) >> 5;
    int lane = threadIdx.x & 31;
    if (w >= N_NODES) return;

    float4 acc = ((const float4*)(g_S + (size_t)w * HID))[lane];
#pragma unroll
    for (int r = 0; r < R_REL; r++) {
        int lo = g_rowptr[r * (N_NODES + 1) + w];
        int hi = g_rowptr[r * (N_NODES + 1) + w + 1];
        if (hi > lo) {
            float inv = 1.0f / (float)(hi - lo);
            float4 s = make_float4(0.f, 0.f, 0.f, 0.f);
            for (int e = lo; e < hi; e++) {
                int src = __ldg(&g_esrc[(size_t)r * N_EDGES + e]);
                const uint2 raw = __ldg((const uint2*)(g_M + ((size_t)r * N_NODES + src) * HID) + lane);
                float2 f0 = __half22float2(*(const __half2*)&raw.x);
                float2 f1 = __half22float2(*(const __half2*)&raw.y);
                s.x += f0.x; s.y += f0.y; s.z += f1.x; s.w += f1.y;
            }
            acc.x += s.x * inv; acc.y += s.y * inv;
            acc.z += s.z * inv; acc.w += s.w * inv;
        }
    }
    acc.x = fmaxf(acc.x, 0.f); acc.y = fmaxf(acc.y, 0.f);
    acc.z = fmaxf(acc.z, 0.f); acc.w = fmaxf(acc.w, 0.f);

    if (FINAL) {
        ((float4*)(g_bufA + (size_t)w * HID))[lane] = acc;
    } else {
        __half2 h0 = __floats2half2_rn(acc.x, acc.y);
        __half2 h1 = __floats2half2_rn(acc.z, acc.w);
        uint2 u = make_uint2(*(uint32_t*)&h0, *(uint32_t*)&h1);
        ((uint2*)(g_Ar + (size_t)w * DPADH))[lane] = u;
    }
}

// ---------------- graph readout (batch sorted; input already relu'd) ----------------
__device__ __forceinline__ int lower_bound_dev(const int* a, int n, int key) {
    int lo = 0, hi = n;
    while (lo < hi) {
        int mid = (lo + hi) >> 1;
        if (a[mid] < key) lo = mid + 1; else hi = mid;
    }
    return lo;
}
__global__ void readout_kernel(const float* __restrict__ h, const int* __restrict__ batch) {
    int g = blockIdx.x;
    int j = threadIdx.x;  // 128
    int lo = lower_bound_dev(batch, N_NODES, g);
    int hi = lower_bound_dev(batch, N_NODES, g + 1);
    float s = 0.0f;
    for (int n = lo; n < hi; n++) s += h[(size_t)n * HID + j];
    int c = hi - lo;
    g_read[g * HID + j] = s / (float)(c > 0 ? c : 1);
}

// ---------------- fused MLP head ----------------
__global__ void mlp_kernel(const float* __restrict__ Wc1, const float* __restrict__ bc1,
                           const float* __restrict__ Wc2, const float* __restrict__ bc2,
                           const float* __restrict__ Wc3, const float* __restrict__ bc3,
                           float* __restrict__ out) {
    int g = blockIdx.x;
    int j = threadIdx.x;  // 128
    __shared__ float row[HID];
    __shared__ float h1[HID];
    __shared__ float h2[HID];

    row[j] = g_read[g * HID + j];
    __syncthreads();

    float acc = bc1[j];
    for (int f = 0; f < HID; f++) acc = fmaf(row[f], Wc1[f * HID + j], acc);
    h1[j] = fmaxf(acc, 0.f);
    __syncthreads();

    acc = bc2[j];
    for (int f = 0; f < HID; f++) acc = fmaf(h1[f], Wc2[f * HID + j], acc);
    h2[j] = fmaxf(acc, 0.f) * Wc3[j];
    __syncthreads();

    for (int s = 64; s > 0; s >>= 1) {
        if (j < s) h2[j] += h2[j + s];
        __syncthreads();
    }
    if (j == 0) out[g] = h2[0] + bc3[0];
}

// ---------------- launch ----------------
extern "C" void kernel_launch(void* const* d_in, const int* in_sizes, int n_in,
                              void* d_out, int out_size) {
    const float* X = (const float*)d_in[0];
    const int* e[R_REL];
    const int* batch;
    if (in_sizes[1] == 2 * N_EDGES) {
        for (int r = 0; r < R_REL; r++) e[r] = (const int*)d_in[1 + r];
        batch = (const int*)d_in[6];
    } else {
        batch = (const int*)d_in[1];
        for (int r = 0; r < R_REL; r++) e[r] = (const int*)d_in[2 + r];
    }
    const float* W0    = (const float*)d_in[7];
    const float* root0 = (const float*)d_in[8];
    const float* b0    = (const float*)d_in[9];
    const float* Wl    = (const float*)d_in[10];
    const float* rootl = (const float*)d_in[11];
    const float* bl    = (const float*)d_in[12];
    const float* Wc1   = (const float*)d_in[13];
    const float* bc1   = (const float*)d_in[14];
    const float* Wc2   = (const float*)d_in[15];
    const float* bc2   = (const float*)d_in[16];
    const float* Wc3   = (const float*)d_in[17];
    const float* bc3   = (const float*)d_in[18];
    float*       out   = (float*)d_out;

    float* bufA; cudaGetSymbolAddress((void**)&bufA, g_bufA);
    float* bufS; cudaGetSymbolAddress((void**)&bufS, g_S);

    cudaFuncSetAttribute(gemm_mma_kernel, cudaFuncAttributeMaxDynamicSharedMemorySize, GEMM_SMEM);

    const int gemmRows = (N_NODES + 127) / 128;  // 782
    dim3 gemmGrid(NBLK, gemmRows);
    dim3 tpBlock(32, 8);
    const int r0Blocks = (int)(((size_t)N_NODES * DPAD0 + 1023) / 1024);
    const int aggBlocks = (N_NODES * 32 + 255) / 256;   // warp per node
    dim3 edgeGrid((N_EDGES + 255) / 256, R_REL);

    // --- layer 0 GEMM first (capture slot), CSR setup after ---
    transpose_kernel<<<dim3(DPAD0 / 32, 4, NBLK), tpBlock>>>(root0, W0, IN_DIM, DPAD0);
    round0_kernel<<<r0Blocks, 1024>>>(X);
    zero_cnt_kernel<<<(R_REL * N_NODES + 255) / 256, 256>>>();
    gemm_mma_kernel<<<gemmGrid, 256, GEMM_SMEM>>>(DPAD0, b0, bufS);

    // dst-CSR: counts -> 3-phase scan -> placement
    count_kernel<<<edgeGrid, 256>>>(e[0], e[1], e[2], e[3], e[4]);
    blocksum_kernel<<<dim3(NCH, R_REL), 256>>>();
    scanb_kernel<<<R_REL, 32>>>();
    rowptr_kernel<<<dim3(NCH, R_REL), 1024>>>();
    place_kernel<<<edgeGrid, 256>>>(e[0], e[1], e[2], e[3], e[4]);

    // layer 0 aggregate -> g_Ar (fp16, stride DPADH)
    aggregate_kernel<false><<<aggBlocks, 256>>>();

    // layer 1
    transpose_kernel<<<dim3(DPADH / 32, 4, NBLK), tpBlock>>>(rootl, Wl, HID, DPADH);
    gemm_mma_kernel<<<gemmGrid, 256, GEMM_SMEM>>>(DPADH, bl, bufS);
    aggregate_kernel<false><<<aggBlocks, 256>>>();

    // layer 2
    transpose_kernel<<<dim3(DPADH / 32, 4, NBLK), tpBlock>>>(rootl + (size_t)HID * HID,
                                                             Wl + (size_t)R_REL * HID * HID,
                                                             HID, DPADH);
    gemm_mma_kernel<<<gemmGrid, 256, GEMM_SMEM>>>(DPADH, bl + HID, bufS);
    aggregate_kernel<true><<<aggBlocks, 256>>>();

    // readout + MLP head
    readout_kernel<<<N_GRAPH, HID>>>(bufA, batch);
    mlp_kernel<<<N_GRAPH, HID>>>(Wc1, bc1, Wc2, bc2, Wc3, bc3, out);
}